// round 10
// baseline (speedup 1.0000x reference)
#include <cuda_runtime.h>
#include <cuda_bf16.h>
#include <math.h>
#include <stdint.h>

#define EMBED 3072
#define NQ 32
#define NKV 8
#define HD 96
#define BATCH 2
#define SEQ 2048
#define ROWS (BATCH*SEQ)                 // 4096
#define QKV_N (NQ*HD + 2*NKV*HD)         // 4608
#define KOFF (NQ*HD)                     // 3072
#define VOFF (NQ*HD + NKV*HD)            // 3840
#define GROUPS (NQ/NKV)                  // 4

// Scratch (allocation-free rule: __device__ globals)
__device__ float g_qkv[ROWS * QKV_N];            // fp32 qkv (rope applied here)
__device__ float g_attn[ROWS * EMBED];           // fp32 attention output
// pre-split bf16 operands (hi / mid)
__device__ __nv_bfloat16 g_xh[ROWS * EMBED],   g_xm[ROWS * EMBED];
__device__ __nv_bfloat16 g_wqh[QKV_N * EMBED], g_wqm[QKV_N * EMBED];
__device__ __nv_bfloat16 g_woh[EMBED * EMBED], g_wom[EMBED * EMBED];
__device__ __nv_bfloat16 g_ah[ROWS * EMBED],   g_am[ROWS * EMBED];

// ---------------------------------------------------------------------------
// Common helpers
// ---------------------------------------------------------------------------
__device__ __forceinline__ void mma_bf16(float* d, const uint32_t* a, const uint32_t* b) {
    asm volatile(
        "mma.sync.aligned.m16n8k16.row.col.f32.bf16.bf16.f32 "
        "{%0,%1,%2,%3}, {%4,%5,%6,%7}, {%8,%9}, {%0,%1,%2,%3};"
        : "+f"(d[0]), "+f"(d[1]), "+f"(d[2]), "+f"(d[3])
        : "r"(a[0]), "r"(a[1]), "r"(a[2]), "r"(a[3]), "r"(b[0]), "r"(b[1]));
}

__device__ __forceinline__ void split2(float x, float y, uint32_t& hi, uint32_t& mid) {
    __nv_bfloat16 hx = __float2bfloat16(x);
    __nv_bfloat16 hy = __float2bfloat16(y);
    __nv_bfloat16 mx = __float2bfloat16(x - __bfloat162float(hx));
    __nv_bfloat16 my = __float2bfloat16(y - __bfloat162float(hy));
    hi  = ((uint32_t)__bfloat16_as_ushort(hy) << 16) | __bfloat16_as_ushort(hx);
    mid = ((uint32_t)__bfloat16_as_ushort(my) << 16) | __bfloat16_as_ushort(mx);
}

__device__ __forceinline__ void cp16(void* smem_ptr, const void* gmem_ptr) {
    uint32_t s = (uint32_t)__cvta_generic_to_shared(smem_ptr);
    asm volatile("cp.async.cg.shared.global [%0], [%1], 16;\n" :: "r"(s), "l"(gmem_ptr));
}
#define CP_COMMIT() asm volatile("cp.async.commit_group;\n" ::: "memory")
#define CP_WAIT0()  asm volatile("cp.async.wait_group 0;\n" ::: "memory")

// ---------------------------------------------------------------------------
// fp32 -> bf16 hi/mid split (elementwise, vectorized by 4)
// ---------------------------------------------------------------------------
__global__ void split_kernel(const float* __restrict__ src,
                             __nv_bfloat16* __restrict__ hi,
                             __nv_bfloat16* __restrict__ mid, int n4)
{
    int i = blockIdx.x * blockDim.x + threadIdx.x;
    if (i >= n4) return;
    float4 v = ((const float4*)src)[i];
    uint2 h, m;
    split2(v.x, v.y, h.x, m.x);
    split2(v.z, v.w, h.y, m.y);
    ((uint2*)hi)[i]  = h;
    ((uint2*)mid)[i] = m;
}

// ---------------------------------------------------------------------------
// Pre-split bf16 GEMM, cp.async double-buffered.
// C[M,N] = (Ahi+Ami)[M,K] * (Bhi+Bmi)[N,K]^T  via 3 MMA terms.
// CTA 128x128, BK=32, 8 warps (4x2), warp tile 32x64, 2 smem stages.
// ---------------------------------------------------------------------------
#define BM 128
#define BN 128
#define BK 32
#define SB 40                    // smem row stride (bf16)
#define ARR (128 * SB)           // one array (bf16 elems)
#define STG (4 * ARR)            // one stage: Ahi,Ami,Bhi,Bmi
#define GEMM_SMEM_BYTES (2 * STG * 2)

__global__ __launch_bounds__(256, 2) void gemm_pre(const __nv_bfloat16* __restrict__ Ah,
                                                   const __nv_bfloat16* __restrict__ Am,
                                                   const __nv_bfloat16* __restrict__ Bh,
                                                   const __nv_bfloat16* __restrict__ Bm,
                                                   float* __restrict__ C,
                                                   int M, int N, int K)
{
    extern __shared__ __nv_bfloat16 smem[];

    const int tid  = threadIdx.x;
    const int warp = tid >> 5;
    const int lane = tid & 31;
    const int m0 = blockIdx.y * BM;
    const int n0 = blockIdx.x * BN;

    const int wm = (warp >> 1) * 32;
    const int wn = (warp & 1) * 64;
    const int g  = lane >> 2;
    const int t4 = lane & 3;

    // cp.async mapping: row = tid>>1 (0..127), col half = (tid&1)*16
    const int lrow = tid >> 1;
    const int lco  = (tid & 1) * 16;

    float acc[2][8][4];
#pragma unroll
    for (int mf = 0; mf < 2; mf++)
#pragma unroll
        for (int nf = 0; nf < 8; nf++)
#pragma unroll
            for (int r = 0; r < 4; r++) acc[mf][nf][r] = 0.0f;

    const size_t arow = (size_t)(m0 + lrow) * K;
    const size_t brow = (size_t)(n0 + lrow) * K;

    // tile loader: 8x cp.async of 16B
    auto load_tile = [&](int k0, int stage) {
        __nv_bfloat16* s = smem + stage * STG;
        const int so = lrow * SB + lco;
        cp16(&s[so],             Ah + arow + k0 + lco);
        cp16(&s[so + 8],         Ah + arow + k0 + lco + 8);
        cp16(&s[ARR + so],       Am + arow + k0 + lco);
        cp16(&s[ARR + so + 8],   Am + arow + k0 + lco + 8);
        cp16(&s[2*ARR + so],     Bh + brow + k0 + lco);
        cp16(&s[2*ARR + so + 8], Bh + brow + k0 + lco + 8);
        cp16(&s[3*ARR + so],     Bm + brow + k0 + lco);
        cp16(&s[3*ARR + so + 8], Bm + brow + k0 + lco + 8);
    };

    const int T = K / BK;
    load_tile(0, 0);
    CP_COMMIT();

    for (int t = 0; t < T; t++) {
        CP_WAIT0();
        __syncthreads();
        if (t + 1 < T) {
            load_tile((t + 1) * BK, (t + 1) & 1);
            CP_COMMIT();
        }

        const __nv_bfloat16* sAh = smem + (t & 1) * STG;
        const __nv_bfloat16* sAm = sAh + ARR;
        const __nv_bfloat16* sBh = sAm + ARR;
        const __nv_bfloat16* sBm = sBh + ARR;

#pragma unroll
        for (int ks = 0; ks < 2; ks++) {
            const int kk = ks * 16 + 2 * t4;

            uint32_t ahi[2][4], ami[2][4];
#pragma unroll
            for (int mf = 0; mf < 2; mf++) {
                const int r = wm + mf * 16 + g;
                ahi[mf][0] = *(const uint32_t*)&sAh[r * SB + kk];
                ahi[mf][1] = *(const uint32_t*)&sAh[(r + 8) * SB + kk];
                ahi[mf][2] = *(const uint32_t*)&sAh[r * SB + kk + 8];
                ahi[mf][3] = *(const uint32_t*)&sAh[(r + 8) * SB + kk + 8];
                ami[mf][0] = *(const uint32_t*)&sAm[r * SB + kk];
                ami[mf][1] = *(const uint32_t*)&sAm[(r + 8) * SB + kk];
                ami[mf][2] = *(const uint32_t*)&sAm[r * SB + kk + 8];
                ami[mf][3] = *(const uint32_t*)&sAm[(r + 8) * SB + kk + 8];
            }

#pragma unroll
            for (int nf = 0; nf < 8; nf++) {
                const int c = wn + nf * 8 + g;
                uint32_t bh[2], bm_[2];
                bh[0]  = *(const uint32_t*)&sBh[c * SB + kk];
                bh[1]  = *(const uint32_t*)&sBh[c * SB + kk + 8];
                bm_[0] = *(const uint32_t*)&sBm[c * SB + kk];
                bm_[1] = *(const uint32_t*)&sBm[c * SB + kk + 8];
                // term-major order: same-acc MMAs at distance 2 (less RAW stall)
                mma_bf16(acc[0][nf], ahi[0], bh);
                mma_bf16(acc[1][nf], ahi[1], bh);
                mma_bf16(acc[0][nf], ami[0], bh);
                mma_bf16(acc[1][nf], ami[1], bh);
                mma_bf16(acc[0][nf], ahi[0], bm_);
                mma_bf16(acc[1][nf], ahi[1], bm_);
            }
        }
        __syncthreads();
    }

#pragma unroll
    for (int mf = 0; mf < 2; mf++) {
#pragma unroll
        for (int nf = 0; nf < 8; nf++) {
            const int r = m0 + wm + mf * 16 + g;
            const int c = n0 + wn + nf * 8 + 2 * t4;
            float2 v0 = {acc[mf][nf][0], acc[mf][nf][1]};
            float2 v1 = {acc[mf][nf][2], acc[mf][nf][3]};
            *(float2*)(C + (size_t)r * N + c)       = v0;
            *(float2*)(C + (size_t)(r + 8) * N + c) = v1;
        }
    }
}

// ---------------------------------------------------------------------------
// RoPE applied in-place to Q (heads 0..31) and K (heads 32..39) of g_qkv.
// ---------------------------------------------------------------------------
__global__ void rope_kernel(float* __restrict__ qkv,
                            const int* __restrict__ positions)
{
    const int total = ROWS * (NQ + NKV) * (HD / 2);
    int idx = blockIdx.x * blockDim.x + threadIdx.x;
    if (idx >= total) return;

    const int i   = idx % (HD / 2);
    const int h   = (idx / (HD / 2)) % (NQ + NKV);
    const int row = idx / ((HD / 2) * (NQ + NKV));

    const int pos = positions[row & (SEQ - 1)];
    const float e = (float)(2 * i) / (float)HD;
    const float inv_freq = expf(-e * 9.210340371976184f);
    const float ang = (float)pos * inv_freq;
    float s, c;
    sincosf(ang, &s, &c);

    float* base = qkv + (size_t)row * QKV_N + h * HD + i;
    const float t1 = base[0];
    const float t2 = base[HD / 2];
    base[0]      = t1 * c - t2 * s;
    base[HD / 2] = t2 * c + t1 * s;
}

// ---------------------------------------------------------------------------
// Causal GQA flash attention with bf16 MMA + 3-term split (unchanged from R8).
// ---------------------------------------------------------------------------
#define AQS 104
#define AVS 72
#define ATTN_SM_BYTES ((4*64*AQS + 2*96*AVS + 2*64*AVS) * 2 + 2 * 128 * 4)

__global__ __launch_bounds__(256, 2) void attn_mma(const float* __restrict__ qkv,
                                                   float* __restrict__ out)
{
    extern __shared__ char sm_raw[];
    __nv_bfloat16* Qhi = (__nv_bfloat16*)sm_raw;
    __nv_bfloat16* Qmi = Qhi + 64 * AQS;
    __nv_bfloat16* Khi = Qmi + 64 * AQS;
    __nv_bfloat16* Kmi = Khi + 64 * AQS;
    __nv_bfloat16* Vhi = Kmi + 64 * AQS;
    __nv_bfloat16* Vmi = Vhi + 96 * AVS;
    __nv_bfloat16* Phi = Vmi + 96 * AVS;
    __nv_bfloat16* Pmi = Phi + 64 * AVS;
    float* redM = (float*)(Pmi + 64 * AVS);
    float* redL = redM + 128;

    const int qb = blockIdx.x;
    const int qh = blockIdx.y;
    const int bb = blockIdx.z;
    const int kvh = qh >> 2;
    const int tid = threadIdx.x, warp = tid >> 5, lane = tid & 31;
    const int wy = warp >> 1, wx = warp & 1;
    const int g = lane >> 2, t4 = lane & 3;
    const int r0 = wy * 16 + g, r1 = r0 + 8;
    const float scale = 0.10206207261596577f;

    for (int idx = tid; idx < 1536; idx += 256) {
        const int r = idx / 24, d = (idx % 24) * 4;
        float4 v = *(const float4*)(qkv + (size_t)(bb * SEQ + qb * 64 + r) * QKV_N + qh * HD + d);
        uint2 h, m;
        split2(v.x, v.y, h.x, m.x);
        split2(v.z, v.w, h.y, m.y);
        *(uint2*)&Qhi[r * AQS + d] = h;
        *(uint2*)&Qmi[r * AQS + d] = m;
    }

    float accO[6][4];
#pragma unroll
    for (int nf = 0; nf < 6; nf++)
#pragma unroll
        for (int e = 0; e < 4; e++) accO[nf][e] = 0.0f;
    float m_run0 = -1e30f, m_run1 = -1e30f, l_run0 = 0.0f, l_run1 = 0.0f;

    for (int kb = 0; kb <= qb; kb++) {
        __syncthreads();

        for (int idx = tid; idx < 1536; idx += 256) {
            const int r = idx / 24, d = (idx % 24) * 4;
            const float* p = qkv + (size_t)(bb * SEQ + kb * 64 + r) * QKV_N + kvh * HD + d;
            float4 kv = *(const float4*)(p + KOFF);
            float4 vv = *(const float4*)(p + VOFF);
            uint2 h, m;
            split2(kv.x, kv.y, h.x, m.x);
            split2(kv.z, kv.w, h.y, m.y);
            *(uint2*)&Khi[r * AQS + d] = h;
            *(uint2*)&Kmi[r * AQS + d] = m;
            float vs[4] = {vv.x, vv.y, vv.z, vv.w};
#pragma unroll
            for (int i = 0; i < 4; i++) {
                __nv_bfloat16 hb = __float2bfloat16(vs[i]);
                Vhi[(d + i) * AVS + r] = hb;
                Vmi[(d + i) * AVS + r] = __float2bfloat16(vs[i] - __bfloat162float(hb));
            }
        }
        __syncthreads();

        float s[4][4];
#pragma unroll
        for (int nf = 0; nf < 4; nf++)
#pragma unroll
            for (int e = 0; e < 4; e++) s[nf][e] = 0.0f;

#pragma unroll
        for (int ks = 0; ks < 6; ks++) {
            const int kk = ks * 16 + 2 * t4;
            uint32_t ah[4], am[4];
            ah[0] = *(const uint32_t*)&Qhi[r0 * AQS + kk];
            ah[1] = *(const uint32_t*)&Qhi[r1 * AQS + kk];
            ah[2] = *(const uint32_t*)&Qhi[r0 * AQS + kk + 8];
            ah[3] = *(const uint32_t*)&Qhi[r1 * AQS + kk + 8];
            am[0] = *(const uint32_t*)&Qmi[r0 * AQS + kk];
            am[1] = *(const uint32_t*)&Qmi[r1 * AQS + kk];
            am[2] = *(const uint32_t*)&Qmi[r0 * AQS + kk + 8];
            am[3] = *(const uint32_t*)&Qmi[r1 * AQS + kk + 8];
#pragma unroll
            for (int nf = 0; nf < 4; nf++) {
                const int c = wx * 32 + nf * 8 + g;
                uint32_t bh[2], bm_[2];
                bh[0]  = *(const uint32_t*)&Khi[c * AQS + kk];
                bh[1]  = *(const uint32_t*)&Khi[c * AQS + kk + 8];
                bm_[0] = *(const uint32_t*)&Kmi[c * AQS + kk];
                bm_[1] = *(const uint32_t*)&Kmi[c * AQS + kk + 8];
                mma_bf16(s[nf], ah, bh);
                mma_bf16(s[nf], am, bh);
                mma_bf16(s[nf], ah, bm_);
            }
        }

        const int rowg0 = qb * 64 + r0, rowg1 = qb * 64 + r1;
#pragma unroll
        for (int nf = 0; nf < 4; nf++) {
            const int cg = kb * 64 + wx * 32 + nf * 8 + 2 * t4;
            s[nf][0] = (cg     > rowg0) ? -1e30f : s[nf][0] * scale;
            s[nf][1] = (cg + 1 > rowg0) ? -1e30f : s[nf][1] * scale;
            s[nf][2] = (cg     > rowg1) ? -1e30f : s[nf][2] * scale;
            s[nf][3] = (cg + 1 > rowg1) ? -1e30f : s[nf][3] * scale;
        }

        float mr0 = s[0][0], mr1 = s[0][2];
#pragma unroll
        for (int nf = 0; nf < 4; nf++) {
            mr0 = fmaxf(mr0, fmaxf(s[nf][0], s[nf][1]));
            mr1 = fmaxf(mr1, fmaxf(s[nf][2], s[nf][3]));
        }
        mr0 = fmaxf(mr0, __shfl_xor_sync(0xffffffffu, mr0, 1));
        mr0 = fmaxf(mr0, __shfl_xor_sync(0xffffffffu, mr0, 2));
        mr1 = fmaxf(mr1, __shfl_xor_sync(0xffffffffu, mr1, 1));
        mr1 = fmaxf(mr1, __shfl_xor_sync(0xffffffffu, mr1, 2));
        if (t4 == 0) {
            redM[wx * 64 + r0] = mr0;
            redM[wx * 64 + r1] = mr1;
        }
        __syncthreads();
        mr0 = fmaxf(mr0, redM[(1 - wx) * 64 + r0]);
        mr1 = fmaxf(mr1, redM[(1 - wx) * 64 + r1]);

        const float mn0 = fmaxf(m_run0, mr0), mn1 = fmaxf(m_run1, mr1);
        const float co0 = __expf(m_run0 - mn0), co1 = __expf(m_run1 - mn1);
        m_run0 = mn0; m_run1 = mn1;

        float sum0 = 0.0f, sum1 = 0.0f;
#pragma unroll
        for (int nf = 0; nf < 4; nf++) {
            s[nf][0] = __expf(s[nf][0] - mn0);
            s[nf][1] = __expf(s[nf][1] - mn0);
            s[nf][2] = __expf(s[nf][2] - mn1);
            s[nf][3] = __expf(s[nf][3] - mn1);
            sum0 += s[nf][0] + s[nf][1];
            sum1 += s[nf][2] + s[nf][3];
            const int c = wx * 32 + nf * 8 + 2 * t4;
            uint32_t hw, mw;
            split2(s[nf][0], s[nf][1], hw, mw);
            *(uint32_t*)&Phi[r0 * AVS + c] = hw;
            *(uint32_t*)&Pmi[r0 * AVS + c] = mw;
            split2(s[nf][2], s[nf][3], hw, mw);
            *(uint32_t*)&Phi[r1 * AVS + c] = hw;
            *(uint32_t*)&Pmi[r1 * AVS + c] = mw;
        }
        sum0 += __shfl_xor_sync(0xffffffffu, sum0, 1);
        sum0 += __shfl_xor_sync(0xffffffffu, sum0, 2);
        sum1 += __shfl_xor_sync(0xffffffffu, sum1, 1);
        sum1 += __shfl_xor_sync(0xffffffffu, sum1, 2);
        if (t4 == 0) {
            redL[wx * 64 + r0] = sum0;
            redL[wx * 64 + r1] = sum1;
        }
        __syncthreads();
        l_run0 = l_run0 * co0 + redL[r0] + redL[64 + r0];
        l_run1 = l_run1 * co1 + redL[r1] + redL[64 + r1];

#pragma unroll
        for (int nf = 0; nf < 6; nf++) {
            accO[nf][0] *= co0; accO[nf][1] *= co0;
            accO[nf][2] *= co1; accO[nf][3] *= co1;
        }
#pragma unroll
        for (int ks = 0; ks < 4; ks++) {
            const int kk = ks * 16 + 2 * t4;
            uint32_t ah[4], am[4];
            ah[0] = *(const uint32_t*)&Phi[r0 * AVS + kk];
            ah[1] = *(const uint32_t*)&Phi[r1 * AVS + kk];
            ah[2] = *(const uint32_t*)&Phi[r0 * AVS + kk + 8];
            ah[3] = *(const uint32_t*)&Phi[r1 * AVS + kk + 8];
            am[0] = *(const uint32_t*)&Pmi[r0 * AVS + kk];
            am[1] = *(const uint32_t*)&Pmi[r1 * AVS + kk];
            am[2] = *(const uint32_t*)&Pmi[r0 * AVS + kk + 8];
            am[3] = *(const uint32_t*)&Pmi[r1 * AVS + kk + 8];
#pragma unroll
            for (int nf = 0; nf < 6; nf++) {
                const int c = wx * 48 + nf * 8 + g;
                uint32_t bh[2], bm_[2];
                bh[0]  = *(const uint32_t*)&Vhi[c * AVS + kk];
                bh[1]  = *(const uint32_t*)&Vhi[c * AVS + kk + 8];
                bm_[0] = *(const uint32_t*)&Vmi[c * AVS + kk];
                bm_[1] = *(const uint32_t*)&Vmi[c * AVS + kk + 8];
                mma_bf16(accO[nf], ah, bh);
                mma_bf16(accO[nf], am, bh);
                mma_bf16(accO[nf], ah, bm_);
            }
        }
    }

    const float il0 = 1.0f / l_run0, il1 = 1.0f / l_run1;
#pragma unroll
    for (int nf = 0; nf < 6; nf++) {
        const int c = qh * HD + wx * 48 + nf * 8 + 2 * t4;
        float2 v0 = {accO[nf][0] * il0, accO[nf][1] * il0};
        float2 v1 = {accO[nf][2] * il1, accO[nf][3] * il1};
        *(float2*)(out + (size_t)(bb * SEQ + qb * 64 + r0) * EMBED + c) = v0;
        *(float2*)(out + (size_t)(bb * SEQ + qb * 64 + r1) * EMBED + c) = v1;
    }
}

// ---------------------------------------------------------------------------
// Launch
// ---------------------------------------------------------------------------
extern "C" void kernel_launch(void* const* d_in, const int* in_sizes, int n_in,
                              void* d_out, int out_size)
{
    const float* x         = (const float*)d_in[0];
    const int*   positions = (const int*)d_in[1];
    const float* W_qkv     = (const float*)d_in[3];
    const float* W_o       = (const float*)d_in[4];
    float* out = (float*)d_out;

    float* qkv;  cudaGetSymbolAddress((void**)&qkv,  g_qkv);
    float* attn; cudaGetSymbolAddress((void**)&attn, g_attn);
    __nv_bfloat16 *xh, *xm, *wqh, *wqm, *woh, *wom, *ah, *am;
    cudaGetSymbolAddress((void**)&xh,  g_xh);   cudaGetSymbolAddress((void**)&xm,  g_xm);
    cudaGetSymbolAddress((void**)&wqh, g_wqh);  cudaGetSymbolAddress((void**)&wqm, g_wqm);
    cudaGetSymbolAddress((void**)&woh, g_woh);  cudaGetSymbolAddress((void**)&wom, g_wom);
    cudaGetSymbolAddress((void**)&ah,  g_ah);   cudaGetSymbolAddress((void**)&am,  g_am);

    cudaFuncSetAttribute(attn_mma, cudaFuncAttributeMaxDynamicSharedMemorySize,
                         ATTN_SM_BYTES);
    cudaFuncSetAttribute(gemm_pre, cudaFuncAttributeMaxDynamicSharedMemorySize,
                         GEMM_SMEM_BYTES);

    // 0) pre-split inputs/weights
    {
        int n4;
        n4 = ROWS * EMBED / 4;
        split_kernel<<<(n4 + 255) / 256, 256>>>(x, xh, xm, n4);
        n4 = QKV_N * EMBED / 4;
        split_kernel<<<(n4 + 255) / 256, 256>>>(W_qkv, wqh, wqm, n4);
        n4 = EMBED * EMBED / 4;
        split_kernel<<<(n4 + 255) / 256, 256>>>(W_o, woh, wom, n4);
    }

    // 1) QKV projection (pre-split bf16, cp.async pipelined)
    gemm_pre<<<dim3(QKV_N / 128, ROWS / 128), 256, GEMM_SMEM_BYTES>>>(
        xh, xm, wqh, wqm, qkv, ROWS, QKV_N, EMBED);

    // 2) RoPE on Q and K in place (fp32)
    {
        const int total = ROWS * (NQ + NKV) * (HD / 2);
        rope_kernel<<<(total + 255) / 256, 256>>>(qkv, positions);
    }

    // 3) Causal GQA attention (bf16 MMA flash)
    attn_mma<<<dim3(SEQ / 64, NQ, BATCH), 256, ATTN_SM_BYTES>>>(qkv, attn);

    // 3b) split attention output for O-proj
    {
        int n4 = ROWS * EMBED / 4;
        split_kernel<<<(n4 + 255) / 256, 256>>>(attn, ah, am, n4);
    }

    // 4) Output projection (pre-split bf16, cp.async pipelined)
    gemm_pre<<<dim3(EMBED / 128, ROWS / 128), 256, GEMM_SMEM_BYTES>>>(
        ah, am, woh, wom, out, ROWS, EMBED, EMBED);
}

// round 12
// speedup vs baseline: 1.0800x; 1.0800x over previous
#include <cuda_runtime.h>
#include <cuda_bf16.h>
#include <math.h>
#include <stdint.h>

#define EMBED 3072
#define NQ 32
#define NKV 8
#define HD 96
#define BATCH 2
#define SEQ 2048
#define ROWS (BATCH*SEQ)                 // 4096
#define QKV_N (NQ*HD + 2*NKV*HD)         // 4608
#define KOFF (NQ*HD)                     // 3072
#define VOFF (NQ*HD + NKV*HD)            // 3840

// Scratch (allocation-free rule: __device__ globals)
__device__ float g_qkv[ROWS * QKV_N];
__device__ float g_attn[ROWS * EMBED];
__device__ __nv_bfloat16 g_xh[ROWS * EMBED],   g_xm[ROWS * EMBED];
__device__ __nv_bfloat16 g_wqh[QKV_N * EMBED], g_wqm[QKV_N * EMBED];
__device__ __nv_bfloat16 g_woh[EMBED * EMBED], g_wom[EMBED * EMBED];
__device__ __nv_bfloat16 g_ah[ROWS * EMBED],   g_am[ROWS * EMBED];

// ---------------------------------------------------------------------------
// Helpers
// ---------------------------------------------------------------------------
__device__ __forceinline__ uint32_t smem_u32(const void* p) {
    return (uint32_t)__cvta_generic_to_shared(p);
}

__device__ __forceinline__ void mma_bf16(float* d, const uint32_t* a, const uint32_t* b) {
    asm volatile(
        "mma.sync.aligned.m16n8k16.row.col.f32.bf16.bf16.f32 "
        "{%0,%1,%2,%3}, {%4,%5,%6,%7}, {%8,%9}, {%0,%1,%2,%3};"
        : "+f"(d[0]), "+f"(d[1]), "+f"(d[2]), "+f"(d[3])
        : "r"(a[0]), "r"(a[1]), "r"(a[2]), "r"(a[3]), "r"(b[0]), "r"(b[1]));
}

__device__ __forceinline__ void ldsm_x4(uint32_t* r, uint32_t addr) {
    asm volatile("ldmatrix.sync.aligned.m8n8.x4.shared.b16 {%0,%1,%2,%3}, [%4];"
                 : "=r"(r[0]), "=r"(r[1]), "=r"(r[2]), "=r"(r[3]) : "r"(addr));
}

__device__ __forceinline__ void split2(float x, float y, uint32_t& hi, uint32_t& mid) {
    __nv_bfloat16 hx = __float2bfloat16(x);
    __nv_bfloat16 hy = __float2bfloat16(y);
    __nv_bfloat16 mx = __float2bfloat16(x - __bfloat162float(hx));
    __nv_bfloat16 my = __float2bfloat16(y - __bfloat162float(hy));
    hi  = ((uint32_t)__bfloat16_as_ushort(hy) << 16) | __bfloat16_as_ushort(hx);
    mid = ((uint32_t)__bfloat16_as_ushort(my) << 16) | __bfloat16_as_ushort(mx);
}

__device__ __forceinline__ void cp16(void* smem_ptr, const void* gmem_ptr) {
    uint32_t s = smem_u32(smem_ptr);
    asm volatile("cp.async.cg.shared.global [%0], [%1], 16;\n" :: "r"(s), "l"(gmem_ptr));
}
#define CP_COMMIT() asm volatile("cp.async.commit_group;\n" ::: "memory")
#define CP_WAIT0()  asm volatile("cp.async.wait_group 0;\n" ::: "memory")

// ---------------------------------------------------------------------------
// fp32 -> bf16 hi/mid split (elementwise)
// ---------------------------------------------------------------------------
__global__ void split_kernel(const float* __restrict__ src,
                             __nv_bfloat16* __restrict__ hi,
                             __nv_bfloat16* __restrict__ mid, int n4)
{
    int i = blockIdx.x * blockDim.x + threadIdx.x;
    if (i >= n4) return;
    float4 v = ((const float4*)src)[i];
    uint2 h, m;
    split2(v.x, v.y, h.x, m.x);
    split2(v.z, v.w, h.y, m.y);
    ((uint2*)hi)[i]  = h;
    ((uint2*)mid)[i] = m;
}

// ---------------------------------------------------------------------------
// Pre-split bf16 GEMM, cp.async double-buffered, ldmatrix fragment loads.
// C[M,N] = (Ahi+Ami)[M,K] * (Bhi+Bmi)[N,K]^T, 3 MMA terms.
// CTA 128x128, BK=32, 8 warps (4x2), warp tile 32x64, 2 smem stages.
// ---------------------------------------------------------------------------
#define BM 128
#define BN 128
#define BK 32
#define SB 40                    // smem row stride (bf16); 80B -> ldmatrix conflict-free
#define ARR (128 * SB)
#define STG (4 * ARR)
#define GEMM_SMEM_BYTES (2 * STG * 2)

__global__ __launch_bounds__(256, 2) void gemm_pre(const __nv_bfloat16* __restrict__ Ah,
                                                   const __nv_bfloat16* __restrict__ Am,
                                                   const __nv_bfloat16* __restrict__ Bh,
                                                   const __nv_bfloat16* __restrict__ Bm,
                                                   float* __restrict__ C,
                                                   int M, int N, int K)
{
    extern __shared__ __nv_bfloat16 smem[];

    const int tid  = threadIdx.x;
    const int warp = tid >> 5;
    const int lane = tid & 31;
    const int m0 = blockIdx.y * BM;
    const int n0 = blockIdx.x * BN;

    const int wm = (warp >> 1) * 32;
    const int wn = (warp & 1) * 64;
    const int g  = lane >> 2;
    const int t4 = lane & 3;

    // ldmatrix lane geometry
    const int l7   = lane & 7;
    const int l8r  = lane & 8;            // +8 rows (A) / +8 cols (B)
    const int l16h = (lane & 16) >> 1;    // +8 cols (A) / +8 rows (B)

    // cp.async mapping: row = tid>>1 (0..127), col half = (tid&1)*16
    const int lrow = tid >> 1;
    const int lco  = (tid & 1) * 16;

    float acc[2][8][4];
#pragma unroll
    for (int mf = 0; mf < 2; mf++)
#pragma unroll
        for (int nf = 0; nf < 8; nf++)
#pragma unroll
            for (int r = 0; r < 4; r++) acc[mf][nf][r] = 0.0f;

    const size_t arow = (size_t)(m0 + lrow) * K;
    const size_t brow = (size_t)(n0 + lrow) * K;

    auto load_tile = [&](int k0, int stage) {
        __nv_bfloat16* s = smem + stage * STG;
        const int so = lrow * SB + lco;
        cp16(&s[so],             Ah + arow + k0 + lco);
        cp16(&s[so + 8],         Ah + arow + k0 + lco + 8);
        cp16(&s[ARR + so],       Am + arow + k0 + lco);
        cp16(&s[ARR + so + 8],   Am + arow + k0 + lco + 8);
        cp16(&s[2*ARR + so],     Bh + brow + k0 + lco);
        cp16(&s[2*ARR + so + 8], Bh + brow + k0 + lco + 8);
        cp16(&s[3*ARR + so],     Bm + brow + k0 + lco);
        cp16(&s[3*ARR + so + 8], Bm + brow + k0 + lco + 8);
    };

    const int T = K / BK;
    load_tile(0, 0);
    CP_COMMIT();

    for (int t = 0; t < T; t++) {
        CP_WAIT0();
        __syncthreads();
        if (t + 1 < T) {
            load_tile((t + 1) * BK, (t + 1) & 1);
            CP_COMMIT();
        }

        const __nv_bfloat16* base = smem + (t & 1) * STG;
        // per-array ldmatrix base addresses (bytes)
        // A: row = wm + mf*16 + l7 + l8r ; col = l16h (+k)
        // B: row = wn + nfp*16 + l7 + l16h ; col = l8r (+k)
        const uint32_t aAh = smem_u32(base) + ((wm + l7 + l8r) * SB + l16h) * 2;
        const uint32_t aAm = aAh + ARR * 2;
        const uint32_t aBh = smem_u32(base) + (2 * ARR + (wn + l7 + l16h) * SB + l8r) * 2;
        const uint32_t aBm = aBh + ARR * 2;

#pragma unroll
        for (int ks = 0; ks < 2; ks++) {
            const uint32_t ko = ks * 32;   // 16 bf16 = 32 bytes

            uint32_t ahi[2][4], ami[2][4];
#pragma unroll
            for (int mf = 0; mf < 2; mf++) {
                ldsm_x4(ahi[mf], aAh + mf * (16 * SB * 2) + ko);
                ldsm_x4(ami[mf], aAm + mf * (16 * SB * 2) + ko);
            }

#pragma unroll
            for (int nfp = 0; nfp < 4; nfp++) {
                uint32_t bh[4], bm[4];
                ldsm_x4(bh, aBh + nfp * (16 * SB * 2) + ko);
                ldsm_x4(bm, aBm + nfp * (16 * SB * 2) + ko);
                const int n0f = nfp * 2, n1f = n0f + 1;
                // hi*hi
                mma_bf16(acc[0][n0f], ahi[0], bh);
                mma_bf16(acc[1][n0f], ahi[1], bh);
                mma_bf16(acc[0][n1f], ahi[0], bh + 2);
                mma_bf16(acc[1][n1f], ahi[1], bh + 2);
                // mid*hi
                mma_bf16(acc[0][n0f], ami[0], bh);
                mma_bf16(acc[1][n0f], ami[1], bh);
                mma_bf16(acc[0][n1f], ami[0], bh + 2);
                mma_bf16(acc[1][n1f], ami[1], bh + 2);
                // hi*mid
                mma_bf16(acc[0][n0f], ahi[0], bm);
                mma_bf16(acc[1][n0f], ahi[1], bm);
                mma_bf16(acc[0][n1f], ahi[0], bm + 2);
                mma_bf16(acc[1][n1f], ahi[1], bm + 2);
            }
        }
        __syncthreads();
    }

#pragma unroll
    for (int mf = 0; mf < 2; mf++) {
#pragma unroll
        for (int nf = 0; nf < 8; nf++) {
            const int r = m0 + wm + mf * 16 + g;
            const int c = n0 + wn + nf * 8 + 2 * t4;
            float2 v0 = {acc[mf][nf][0], acc[mf][nf][1]};
            float2 v1 = {acc[mf][nf][2], acc[mf][nf][3]};
            *(float2*)(C + (size_t)r * N + c)       = v0;
            *(float2*)(C + (size_t)(r + 8) * N + c) = v1;
        }
    }
}

// ---------------------------------------------------------------------------
// RoPE in-place on Q (heads 0..31) and K (heads 32..39) of g_qkv.
// ---------------------------------------------------------------------------
__global__ void rope_kernel(float* __restrict__ qkv,
                            const int* __restrict__ positions)
{
    const int total = ROWS * (NQ + NKV) * (HD / 2);
    int idx = blockIdx.x * blockDim.x + threadIdx.x;
    if (idx >= total) return;

    const int i   = idx % (HD / 2);
    const int h   = (idx / (HD / 2)) % (NQ + NKV);
    const int row = idx / ((HD / 2) * (NQ + NKV));

    const int pos = positions[row & (SEQ - 1)];
    const float e = (float)(2 * i) / (float)HD;
    const float inv_freq = expf(-e * 9.210340371976184f);
    const float ang = (float)pos * inv_freq;
    float s, c;
    sincosf(ang, &s, &c);

    float* base = qkv + (size_t)row * QKV_N + h * HD + i;
    const float t1 = base[0];
    const float t2 = base[HD / 2];
    base[0]      = t1 * c - t2 * s;
    base[HD / 2] = t2 * c + t1 * s;
}

// ---------------------------------------------------------------------------
// Causal GQA flash attention, bf16 MMA + 3-term split, ldmatrix fragments.
// CTA = 64 q-rows x (head, batch). 8 warps 4x2.
// Strides: Q/K 104 bf16 (208B), V/P 72 bf16 (144B) -> ldmatrix conflict-free.
// ---------------------------------------------------------------------------
#define AQS 104
#define AVS 72
#define ATTN_SM_BYTES ((4*64*AQS + 2*96*AVS + 2*64*AVS) * 2 + 2 * 128 * 4)

__global__ __launch_bounds__(256, 2) void attn_mma(const float* __restrict__ qkv,
                                                   float* __restrict__ out)
{
    extern __shared__ char sm_raw[];
    __nv_bfloat16* Qhi = (__nv_bfloat16*)sm_raw;
    __nv_bfloat16* Qmi = Qhi + 64 * AQS;
    __nv_bfloat16* Khi = Qmi + 64 * AQS;
    __nv_bfloat16* Kmi = Khi + 64 * AQS;
    __nv_bfloat16* Vhi = Kmi + 64 * AQS;
    __nv_bfloat16* Vmi = Vhi + 96 * AVS;
    __nv_bfloat16* Phi = Vmi + 96 * AVS;
    __nv_bfloat16* Pmi = Phi + 64 * AVS;
    float* redM = (float*)(Pmi + 64 * AVS);
    float* redL = redM + 128;

    const int qb = blockIdx.x;
    const int qh = blockIdx.y;
    const int bb = blockIdx.z;
    const int kvh = qh >> 2;
    const int tid = threadIdx.x, warp = tid >> 5, lane = tid & 31;
    const int wy = warp >> 1, wx = warp & 1;
    const int g = lane >> 2, t4 = lane & 3;
    const int r0 = wy * 16 + g, r1 = r0 + 8;
    const float scale = 0.10206207261596577f;

    const int l7   = lane & 7;
    const int l8r  = lane & 8;
    const int l16h = (lane & 16) >> 1;

    // ldmatrix base addresses (constant across kb)
    const uint32_t aQh = smem_u32(Qhi) + ((wy * 16 + l7 + l8r) * AQS + l16h) * 2;
    const uint32_t aQm = aQh + (64 * AQS) * 2;
    const uint32_t aKh = smem_u32(Khi) + ((wx * 32 + l7 + l16h) * AQS + l8r) * 2;
    const uint32_t aKm = aKh + (64 * AQS) * 2;
    const uint32_t aVh = smem_u32(Vhi) + ((wx * 48 + l7 + l16h) * AVS + l8r) * 2;
    const uint32_t aVm = aVh + (96 * AVS) * 2;
    const uint32_t aPh = smem_u32(Phi) + ((wy * 16 + l7 + l8r) * AVS + l16h) * 2;
    const uint32_t aPm = aPh + (64 * AVS) * 2;

    for (int idx = tid; idx < 1536; idx += 256) {
        const int r = idx / 24, d = (idx % 24) * 4;
        float4 v = *(const float4*)(qkv + (size_t)(bb * SEQ + qb * 64 + r) * QKV_N + qh * HD + d);
        uint2 h, m;
        split2(v.x, v.y, h.x, m.x);
        split2(v.z, v.w, h.y, m.y);
        *(uint2*)&Qhi[r * AQS + d] = h;
        *(uint2*)&Qmi[r * AQS + d] = m;
    }

    float accO[6][4];
#pragma unroll
    for (int nf = 0; nf < 6; nf++)
#pragma unroll
        for (int e = 0; e < 4; e++) accO[nf][e] = 0.0f;
    float m_run0 = -1e30f, m_run1 = -1e30f, l_run0 = 0.0f, l_run1 = 0.0f;

    for (int kb = 0; kb <= qb; kb++) {
        __syncthreads();

        for (int idx = tid; idx < 1536; idx += 256) {
            const int r = idx / 24, d = (idx % 24) * 4;
            const float* p = qkv + (size_t)(bb * SEQ + kb * 64 + r) * QKV_N + kvh * HD + d;
            float4 kv = *(const float4*)(p + KOFF);
            float4 vv = *(const float4*)(p + VOFF);
            uint2 h, m;
            split2(kv.x, kv.y, h.x, m.x);
            split2(kv.z, kv.w, h.y, m.y);
            *(uint2*)&Khi[r * AQS + d] = h;
            *(uint2*)&Kmi[r * AQS + d] = m;
            float vs[4] = {vv.x, vv.y, vv.z, vv.w};
#pragma unroll
            for (int i = 0; i < 4; i++) {
                __nv_bfloat16 hb = __float2bfloat16(vs[i]);
                Vhi[(d + i) * AVS + r] = hb;
                Vmi[(d + i) * AVS + r] = __float2bfloat16(vs[i] - __bfloat162float(hb));
            }
        }
        __syncthreads();

        // ---- S = Q K^T ----
        float s[4][4];
#pragma unroll
        for (int nf = 0; nf < 4; nf++)
#pragma unroll
            for (int e = 0; e < 4; e++) s[nf][e] = 0.0f;

#pragma unroll
        for (int ks = 0; ks < 6; ks++) {
            const uint32_t ko = ks * 32;
            uint32_t ah[4], am[4];
            ldsm_x4(ah, aQh + ko);
            ldsm_x4(am, aQm + ko);
#pragma unroll
            for (int nfp = 0; nfp < 2; nfp++) {
                uint32_t bh[4], bm[4];
                ldsm_x4(bh, aKh + nfp * (16 * AQS * 2) + ko);
                ldsm_x4(bm, aKm + nfp * (16 * AQS * 2) + ko);
                const int n0f = nfp * 2, n1f = n0f + 1;
                mma_bf16(s[n0f], ah, bh);
                mma_bf16(s[n1f], ah, bh + 2);
                mma_bf16(s[n0f], am, bh);
                mma_bf16(s[n1f], am, bh + 2);
                mma_bf16(s[n0f], ah, bm);
                mma_bf16(s[n1f], ah, bm + 2);
            }
        }

        const int rowg0 = qb * 64 + r0, rowg1 = qb * 64 + r1;
#pragma unroll
        for (int nf = 0; nf < 4; nf++) {
            const int cg = kb * 64 + wx * 32 + nf * 8 + 2 * t4;
            s[nf][0] = (cg     > rowg0) ? -1e30f : s[nf][0] * scale;
            s[nf][1] = (cg + 1 > rowg0) ? -1e30f : s[nf][1] * scale;
            s[nf][2] = (cg     > rowg1) ? -1e30f : s[nf][2] * scale;
            s[nf][3] = (cg + 1 > rowg1) ? -1e30f : s[nf][3] * scale;
        }

        float mr0 = s[0][0], mr1 = s[0][2];
#pragma unroll
        for (int nf = 0; nf < 4; nf++) {
            mr0 = fmaxf(mr0, fmaxf(s[nf][0], s[nf][1]));
            mr1 = fmaxf(mr1, fmaxf(s[nf][2], s[nf][3]));
        }
        mr0 = fmaxf(mr0, __shfl_xor_sync(0xffffffffu, mr0, 1));
        mr0 = fmaxf(mr0, __shfl_xor_sync(0xffffffffu, mr0, 2));
        mr1 = fmaxf(mr1, __shfl_xor_sync(0xffffffffu, mr1, 1));
        mr1 = fmaxf(mr1, __shfl_xor_sync(0xffffffffu, mr1, 2));
        if (t4 == 0) {
            redM[wx * 64 + r0] = mr0;
            redM[wx * 64 + r1] = mr1;
        }
        __syncthreads();
        mr0 = fmaxf(mr0, redM[(1 - wx) * 64 + r0]);
        mr1 = fmaxf(mr1, redM[(1 - wx) * 64 + r1]);

        const float mn0 = fmaxf(m_run0, mr0), mn1 = fmaxf(m_run1, mr1);
        const float co0 = __expf(m_run0 - mn0), co1 = __expf(m_run1 - mn1);
        m_run0 = mn0; m_run1 = mn1;

        float sum0 = 0.0f, sum1 = 0.0f;
#pragma unroll
        for (int nf = 0; nf < 4; nf++) {
            s[nf][0] = __expf(s[nf][0] - mn0);
            s[nf][1] = __expf(s[nf][1] - mn0);
            s[nf][2] = __expf(s[nf][2] - mn1);
            s[nf][3] = __expf(s[nf][3] - mn1);
            sum0 += s[nf][0] + s[nf][1];
            sum1 += s[nf][2] + s[nf][3];
            const int c = wx * 32 + nf * 8 + 2 * t4;
            uint32_t hw, mw;
            split2(s[nf][0], s[nf][1], hw, mw);
            *(uint32_t*)&Phi[r0 * AVS + c] = hw;
            *(uint32_t*)&Pmi[r0 * AVS + c] = mw;
            split2(s[nf][2], s[nf][3], hw, mw);
            *(uint32_t*)&Phi[r1 * AVS + c] = hw;
            *(uint32_t*)&Pmi[r1 * AVS + c] = mw;
        }
        sum0 += __shfl_xor_sync(0xffffffffu, sum0, 1);
        sum0 += __shfl_xor_sync(0xffffffffu, sum0, 2);
        sum1 += __shfl_xor_sync(0xffffffffu, sum1, 1);
        sum1 += __shfl_xor_sync(0xffffffffu, sum1, 2);
        if (t4 == 0) {
            redL[wx * 64 + r0] = sum0;
            redL[wx * 64 + r1] = sum1;
        }
        __syncthreads();
        l_run0 = l_run0 * co0 + redL[r0] + redL[64 + r0];
        l_run1 = l_run1 * co1 + redL[r1] + redL[64 + r1];

        // ---- O = O*c + P V ----
#pragma unroll
        for (int nf = 0; nf < 6; nf++) {
            accO[nf][0] *= co0; accO[nf][1] *= co0;
            accO[nf][2] *= co1; accO[nf][3] *= co1;
        }
#pragma unroll
        for (int ks = 0; ks < 4; ks++) {
            const uint32_t ko = ks * 32;
            uint32_t ah[4], am[4];
            ldsm_x4(ah, aPh + ko);
            ldsm_x4(am, aPm + ko);
#pragma unroll
            for (int nfp = 0; nfp < 3; nfp++) {
                uint32_t bh[4], bm[4];
                ldsm_x4(bh, aVh + nfp * (16 * AVS * 2) + ko);
                ldsm_x4(bm, aVm + nfp * (16 * AVS * 2) + ko);
                const int n0f = nfp * 2, n1f = n0f + 1;
                mma_bf16(accO[n0f], ah, bh);
                mma_bf16(accO[n1f], ah, bh + 2);
                mma_bf16(accO[n0f], am, bh);
                mma_bf16(accO[n1f], am, bh + 2);
                mma_bf16(accO[n0f], ah, bm);
                mma_bf16(accO[n1f], ah, bm + 2);
            }
        }
    }

    const float il0 = 1.0f / l_run0, il1 = 1.0f / l_run1;
#pragma unroll
    for (int nf = 0; nf < 6; nf++) {
        const int c = qh * HD + wx * 48 + nf * 8 + 2 * t4;
        float2 v0 = {accO[nf][0] * il0, accO[nf][1] * il0};
        float2 v1 = {accO[nf][2] * il1, accO[nf][3] * il1};
        *(float2*)(out + (size_t)(bb * SEQ + qb * 64 + r0) * EMBED + c) = v0;
        *(float2*)(out + (size_t)(bb * SEQ + qb * 64 + r1) * EMBED + c) = v1;
    }
}

// ---------------------------------------------------------------------------
// Launch
// ---------------------------------------------------------------------------
extern "C" void kernel_launch(void* const* d_in, const int* in_sizes, int n_in,
                              void* d_out, int out_size)
{
    const float* x         = (const float*)d_in[0];
    const int*   positions = (const int*)d_in[1];
    const float* W_qkv     = (const float*)d_in[3];
    const float* W_o       = (const float*)d_in[4];
    float* out = (float*)d_out;

    float* qkv;  cudaGetSymbolAddress((void**)&qkv,  g_qkv);
    float* attn; cudaGetSymbolAddress((void**)&attn, g_attn);
    __nv_bfloat16 *xh, *xm, *wqh, *wqm, *woh, *wom, *ah, *am;
    cudaGetSymbolAddress((void**)&xh,  g_xh);   cudaGetSymbolAddress((void**)&xm,  g_xm);
    cudaGetSymbolAddress((void**)&wqh, g_wqh);  cudaGetSymbolAddress((void**)&wqm, g_wqm);
    cudaGetSymbolAddress((void**)&woh, g_woh);  cudaGetSymbolAddress((void**)&wom, g_wom);
    cudaGetSymbolAddress((void**)&ah,  g_ah);   cudaGetSymbolAddress((void**)&am,  g_am);

    cudaFuncSetAttribute(attn_mma, cudaFuncAttributeMaxDynamicSharedMemorySize,
                         ATTN_SM_BYTES);
    cudaFuncSetAttribute(gemm_pre, cudaFuncAttributeMaxDynamicSharedMemorySize,
                         GEMM_SMEM_BYTES);

    // 0) pre-split inputs/weights
    {
        int n4;
        n4 = ROWS * EMBED / 4;
        split_kernel<<<(n4 + 255) / 256, 256>>>(x, xh, xm, n4);
        n4 = QKV_N * EMBED / 4;
        split_kernel<<<(n4 + 255) / 256, 256>>>(W_qkv, wqh, wqm, n4);
        n4 = EMBED * EMBED / 4;
        split_kernel<<<(n4 + 255) / 256, 256>>>(W_o, woh, wom, n4);
    }

    // 1) QKV projection
    gemm_pre<<<dim3(QKV_N / 128, ROWS / 128), 256, GEMM_SMEM_BYTES>>>(
        xh, xm, wqh, wqm, qkv, ROWS, QKV_N, EMBED);

    // 2) RoPE in place
    {
        const int total = ROWS * (NQ + NKV) * (HD / 2);
        rope_kernel<<<(total + 255) / 256, 256>>>(qkv, positions);
    }

    // 3) Causal GQA attention
    attn_mma<<<dim3(SEQ / 64, NQ, BATCH), 256, ATTN_SM_BYTES>>>(qkv, attn);

    // 3b) split attention output for O-proj
    {
        int n4 = ROWS * EMBED / 4;
        split_kernel<<<(n4 + 255) / 256, 256>>>(attn, ah, am, n4);
    }

    // 4) Output projection
    gemm_pre<<<dim3(EMBED / 128, ROWS / 128), 256, GEMM_SMEM_BYTES>>>(
        ah, am, woh, wom, out, ROWS, EMBED, EMBED);
}

// round 13
// speedup vs baseline: 1.3130x; 1.2158x over previous
#include <cuda_runtime.h>
#include <cuda_bf16.h>
#include <math.h>
#include <stdint.h>

#define EMBED 3072
#define NQ 32
#define NKV 8
#define HD 96
#define BATCH 2
#define SEQ 2048
#define ROWS (BATCH*SEQ)                 // 4096
#define QKV_N (NQ*HD + 2*NKV*HD)         // 4608
#define KOFF (NQ*HD)                     // 3072
#define VOFF (NQ*HD + NKV*HD)            // 3840

// Scratch (allocation-free rule: __device__ globals)
__device__ float g_qkv[ROWS * QKV_N];
__device__ __nv_bfloat16 g_xh[ROWS * EMBED],   g_xm[ROWS * EMBED];
__device__ __nv_bfloat16 g_wqh[QKV_N * EMBED], g_wqm[QKV_N * EMBED];
__device__ __nv_bfloat16 g_woh[EMBED * EMBED], g_wom[EMBED * EMBED];
__device__ __nv_bfloat16 g_ah[ROWS * EMBED],   g_am[ROWS * EMBED];   // attn out (pre-split)
// pre-split attention operands
__device__ __nv_bfloat16 g_qsh[ROWS * EMBED],  g_qsm[ROWS * EMBED];  // Q post-rope
__device__ __nv_bfloat16 g_ksh[BATCH*NKV*SEQ*HD], g_ksm[BATCH*NKV*SEQ*HD];
__device__ __nv_bfloat16 g_vsh[BATCH*NKV*SEQ*HD], g_vsm[BATCH*NKV*SEQ*HD];

// ---------------------------------------------------------------------------
// Helpers
// ---------------------------------------------------------------------------
__device__ __forceinline__ uint32_t smem_u32(const void* p) {
    return (uint32_t)__cvta_generic_to_shared(p);
}

__device__ __forceinline__ void mma_bf16(float* d, const uint32_t* a, const uint32_t* b) {
    asm volatile(
        "mma.sync.aligned.m16n8k16.row.col.f32.bf16.bf16.f32 "
        "{%0,%1,%2,%3}, {%4,%5,%6,%7}, {%8,%9}, {%0,%1,%2,%3};"
        : "+f"(d[0]), "+f"(d[1]), "+f"(d[2]), "+f"(d[3])
        : "r"(a[0]), "r"(a[1]), "r"(a[2]), "r"(a[3]), "r"(b[0]), "r"(b[1]));
}

__device__ __forceinline__ void ldsm_x4(uint32_t* r, uint32_t addr) {
    asm volatile("ldmatrix.sync.aligned.m8n8.x4.shared.b16 {%0,%1,%2,%3}, [%4];"
                 : "=r"(r[0]), "=r"(r[1]), "=r"(r[2]), "=r"(r[3]) : "r"(addr));
}

__device__ __forceinline__ void ldsm_x4_t(uint32_t* r, uint32_t addr) {
    asm volatile("ldmatrix.sync.aligned.m8n8.x4.trans.shared.b16 {%0,%1,%2,%3}, [%4];"
                 : "=r"(r[0]), "=r"(r[1]), "=r"(r[2]), "=r"(r[3]) : "r"(addr));
}

__device__ __forceinline__ void split2(float x, float y, uint32_t& hi, uint32_t& mid) {
    __nv_bfloat16 hx = __float2bfloat16(x);
    __nv_bfloat16 hy = __float2bfloat16(y);
    __nv_bfloat16 mx = __float2bfloat16(x - __bfloat162float(hx));
    __nv_bfloat16 my = __float2bfloat16(y - __bfloat162float(hy));
    hi  = ((uint32_t)__bfloat16_as_ushort(hy) << 16) | __bfloat16_as_ushort(hx);
    mid = ((uint32_t)__bfloat16_as_ushort(my) << 16) | __bfloat16_as_ushort(mx);
}

__device__ __forceinline__ void split1(float x, __nv_bfloat16& h, __nv_bfloat16& m) {
    h = __float2bfloat16(x);
    m = __float2bfloat16(x - __bfloat162float(h));
}

__device__ __forceinline__ void cp16(void* smem_ptr, const void* gmem_ptr) {
    uint32_t s = smem_u32(smem_ptr);
    asm volatile("cp.async.cg.shared.global [%0], [%1], 16;\n" :: "r"(s), "l"(gmem_ptr));
}
#define CP_COMMIT() asm volatile("cp.async.commit_group;\n" ::: "memory")
#define CP_WAIT0()  asm volatile("cp.async.wait_group 0;\n" ::: "memory")
#define CP_WAIT1()  asm volatile("cp.async.wait_group 1;\n" ::: "memory")

// ---------------------------------------------------------------------------
// fp32 -> bf16 hi/mid split (elementwise)
// ---------------------------------------------------------------------------
__global__ void split_kernel(const float* __restrict__ src,
                             __nv_bfloat16* __restrict__ hi,
                             __nv_bfloat16* __restrict__ mid, int n4)
{
    int i = blockIdx.x * blockDim.x + threadIdx.x;
    if (i >= n4) return;
    float4 v = ((const float4*)src)[i];
    uint2 h, m;
    split2(v.x, v.y, h.x, m.x);
    split2(v.z, v.w, h.y, m.y);
    ((uint2*)hi)[i]  = h;
    ((uint2*)mid)[i] = m;
}

// ---------------------------------------------------------------------------
// Fused RoPE + split for Q (heads 0..31) and K (heads 32..39).
// Q -> g_qsh/g_qsm [row][qh*96+d]; K -> g_ksh/g_ksm [(bb*8+kvh)*2048+s][96].
// ---------------------------------------------------------------------------
__global__ void rope_split_qk(const float* __restrict__ qkv,
                              const int* __restrict__ positions,
                              __nv_bfloat16* __restrict__ qh_, __nv_bfloat16* __restrict__ qm_,
                              __nv_bfloat16* __restrict__ kh_, __nv_bfloat16* __restrict__ km_)
{
    const int total = ROWS * (NQ + NKV) * (HD / 2);
    int idx = blockIdx.x * blockDim.x + threadIdx.x;
    if (idx >= total) return;

    const int i   = idx % (HD / 2);
    const int h   = (idx / (HD / 2)) % (NQ + NKV);
    const int row = idx / ((HD / 2) * (NQ + NKV));

    const int pos = positions[row & (SEQ - 1)];
    const float e = (float)(2 * i) / (float)HD;
    const float inv_freq = expf(-e * 9.210340371976184f);
    const float ang = (float)pos * inv_freq;
    float s, c;
    sincosf(ang, &s, &c);

    const float* base = qkv + (size_t)row * QKV_N + h * HD + i;
    const float t1 = base[0];
    const float t2 = base[HD / 2];
    const float o1 = t1 * c - t2 * s;
    const float o2 = t2 * c + t1 * s;

    __nv_bfloat16 h1, m1, h2, m2;
    split1(o1, h1, m1);
    split1(o2, h2, m2);

    if (h < NQ) {
        const size_t b = (size_t)row * EMBED + h * HD + i;
        qh_[b] = h1; qm_[b] = m1;
        qh_[b + HD/2] = h2; qm_[b + HD/2] = m2;
    } else {
        const int kvh = h - NQ;
        const int bb = row >> 11, ss = row & (SEQ - 1);
        const size_t b = ((size_t)(bb * NKV + kvh) * SEQ + ss) * HD + i;
        kh_[b] = h1; km_[b] = m1;
        kh_[b + HD/2] = h2; km_[b + HD/2] = m2;
    }
}

// ---------------------------------------------------------------------------
// V split (no rope, row-major [(bb*8+kvh)*2048+s][96]).
// ---------------------------------------------------------------------------
__global__ void split_v(const float* __restrict__ qkv,
                        __nv_bfloat16* __restrict__ vh_, __nv_bfloat16* __restrict__ vm_)
{
    const int total = ROWS * NKV * (HD / 4);
    int idx = blockIdx.x * blockDim.x + threadIdx.x;
    if (idx >= total) return;
    const int d4  = idx % (HD / 4);
    const int kvh = (idx / (HD / 4)) % NKV;
    const int row = idx / ((HD / 4) * NKV);
    const int bb = row >> 11, ss = row & (SEQ - 1);

    float4 v = *(const float4*)(qkv + (size_t)row * QKV_N + VOFF + kvh * HD + d4 * 4);
    uint2 h, m;
    split2(v.x, v.y, h.x, m.x);
    split2(v.z, v.w, h.y, m.y);
    const size_t b = ((size_t)(bb * NKV + kvh) * SEQ + ss) * HD + d4 * 4;
    *(uint2*)&vh_[b] = h;
    *(uint2*)&vm_[b] = m;
}

// ---------------------------------------------------------------------------
// Pre-split bf16 GEMM (unchanged from R11).
// ---------------------------------------------------------------------------
#define BM 128
#define BN 128
#define BK 32
#define SB 40
#define ARR (128 * SB)
#define STG (4 * ARR)
#define GEMM_SMEM_BYTES (2 * STG * 2)

__global__ __launch_bounds__(256, 2) void gemm_pre(const __nv_bfloat16* __restrict__ Ah,
                                                   const __nv_bfloat16* __restrict__ Am,
                                                   const __nv_bfloat16* __restrict__ Bh,
                                                   const __nv_bfloat16* __restrict__ Bm,
                                                   float* __restrict__ C,
                                                   int M, int N, int K)
{
    extern __shared__ __nv_bfloat16 smem[];

    const int tid  = threadIdx.x;
    const int warp = tid >> 5;
    const int lane = tid & 31;
    const int m0 = blockIdx.y * BM;
    const int n0 = blockIdx.x * BN;

    const int wm = (warp >> 1) * 32;
    const int wn = (warp & 1) * 64;
    const int g  = lane >> 2;
    const int t4 = lane & 3;

    const int l7   = lane & 7;
    const int l8r  = lane & 8;
    const int l16h = (lane & 16) >> 1;

    const int lrow = tid >> 1;
    const int lco  = (tid & 1) * 16;

    float acc[2][8][4];
#pragma unroll
    for (int mf = 0; mf < 2; mf++)
#pragma unroll
        for (int nf = 0; nf < 8; nf++)
#pragma unroll
            for (int r = 0; r < 4; r++) acc[mf][nf][r] = 0.0f;

    const size_t arow = (size_t)(m0 + lrow) * K;
    const size_t brow = (size_t)(n0 + lrow) * K;

    auto load_tile = [&](int k0, int stage) {
        __nv_bfloat16* s = smem + stage * STG;
        const int so = lrow * SB + lco;
        cp16(&s[so],             Ah + arow + k0 + lco);
        cp16(&s[so + 8],         Ah + arow + k0 + lco + 8);
        cp16(&s[ARR + so],       Am + arow + k0 + lco);
        cp16(&s[ARR + so + 8],   Am + arow + k0 + lco + 8);
        cp16(&s[2*ARR + so],     Bh + brow + k0 + lco);
        cp16(&s[2*ARR + so + 8], Bh + brow + k0 + lco + 8);
        cp16(&s[3*ARR + so],     Bm + brow + k0 + lco);
        cp16(&s[3*ARR + so + 8], Bm + brow + k0 + lco + 8);
    };

    const int T = K / BK;
    load_tile(0, 0);
    CP_COMMIT();

    for (int t = 0; t < T; t++) {
        CP_WAIT0();
        __syncthreads();
        if (t + 1 < T) {
            load_tile((t + 1) * BK, (t + 1) & 1);
            CP_COMMIT();
        }

        const __nv_bfloat16* base = smem + (t & 1) * STG;
        const uint32_t aAh = smem_u32(base) + ((wm + l7 + l8r) * SB + l16h) * 2;
        const uint32_t aAm = aAh + ARR * 2;
        const uint32_t aBh = smem_u32(base) + (2 * ARR + (wn + l7 + l16h) * SB + l8r) * 2;
        const uint32_t aBm = aBh + ARR * 2;

#pragma unroll
        for (int ks = 0; ks < 2; ks++) {
            const uint32_t ko = ks * 32;

            uint32_t ahi[2][4], ami[2][4];
#pragma unroll
            for (int mf = 0; mf < 2; mf++) {
                ldsm_x4(ahi[mf], aAh + mf * (16 * SB * 2) + ko);
                ldsm_x4(ami[mf], aAm + mf * (16 * SB * 2) + ko);
            }

#pragma unroll
            for (int nfp = 0; nfp < 4; nfp++) {
                uint32_t bh[4], bm[4];
                ldsm_x4(bh, aBh + nfp * (16 * SB * 2) + ko);
                ldsm_x4(bm, aBm + nfp * (16 * SB * 2) + ko);
                const int n0f = nfp * 2, n1f = n0f + 1;
                mma_bf16(acc[0][n0f], ahi[0], bh);
                mma_bf16(acc[1][n0f], ahi[1], bh);
                mma_bf16(acc[0][n1f], ahi[0], bh + 2);
                mma_bf16(acc[1][n1f], ahi[1], bh + 2);
                mma_bf16(acc[0][n0f], ami[0], bh);
                mma_bf16(acc[1][n0f], ami[1], bh);
                mma_bf16(acc[0][n1f], ami[0], bh + 2);
                mma_bf16(acc[1][n1f], ami[1], bh + 2);
                mma_bf16(acc[0][n0f], ahi[0], bm);
                mma_bf16(acc[1][n0f], ahi[1], bm);
                mma_bf16(acc[0][n1f], ahi[0], bm + 2);
                mma_bf16(acc[1][n1f], ahi[1], bm + 2);
            }
        }
        __syncthreads();
    }

#pragma unroll
    for (int mf = 0; mf < 2; mf++) {
#pragma unroll
        for (int nf = 0; nf < 8; nf++) {
            const int r = m0 + wm + mf * 16 + g;
            const int c = n0 + wn + nf * 8 + 2 * t4;
            float2 v0 = {acc[mf][nf][0], acc[mf][nf][1]};
            float2 v1 = {acc[mf][nf][2], acc[mf][nf][3]};
            *(float2*)(C + (size_t)r * N + c)       = v0;
            *(float2*)(C + (size_t)(r + 8) * N + c) = v1;
        }
    }
}

// ---------------------------------------------------------------------------
// Causal GQA flash attention: pre-split operands, cp.async pipelined tiles,
// ldmatrix(+trans for V) fragments, bf16-split output.
// Strides: Q/K/V 104 bf16 rows, P 72.
// ---------------------------------------------------------------------------
#define AQS 104
#define APS 72
#define ATTN_SM_BYTES ((6*64*AQS + 2*64*APS) * 2 + 2 * 128 * 4)   // 99,328 B

__global__ __launch_bounds__(256, 2) void attn_mma(
    const __nv_bfloat16* __restrict__ qh_, const __nv_bfloat16* __restrict__ qm_,
    const __nv_bfloat16* __restrict__ kh_, const __nv_bfloat16* __restrict__ km_,
    const __nv_bfloat16* __restrict__ vh_, const __nv_bfloat16* __restrict__ vm_,
    __nv_bfloat16* __restrict__ outH, __nv_bfloat16* __restrict__ outM)
{
    extern __shared__ char sm_raw[];
    __nv_bfloat16* Qhi = (__nv_bfloat16*)sm_raw;
    __nv_bfloat16* Qmi = Qhi + 64 * AQS;
    __nv_bfloat16* Khi = Qmi + 64 * AQS;
    __nv_bfloat16* Kmi = Khi + 64 * AQS;
    __nv_bfloat16* Vhi = Kmi + 64 * AQS;
    __nv_bfloat16* Vmi = Vhi + 64 * AQS;
    __nv_bfloat16* Phi = Vmi + 64 * AQS;
    __nv_bfloat16* Pmi = Phi + 64 * APS;
    float* redM = (float*)(Pmi + 64 * APS);
    float* redL = redM + 128;

    const int qb = blockIdx.x;
    const int qh = blockIdx.y;
    const int bb = blockIdx.z;
    const int kvh = qh >> 2;
    const int tid = threadIdx.x, warp = tid >> 5, lane = tid & 31;
    const int wy = warp >> 1, wx = warp & 1;
    const int g = lane >> 2, t4 = lane & 3;
    const int r0 = wy * 16 + g, r1 = r0 + 8;
    const float scale = 0.10206207261596577f;

    const int l7   = lane & 7;
    const int l8r  = lane & 8;
    const int l16h = (lane & 16) >> 1;

    // fragment base addresses
    const uint32_t aQh = smem_u32(Qhi) + ((wy * 16 + l7 + l8r) * AQS + l16h) * 2;
    const uint32_t aQm = aQh + (64 * AQS) * 2;
    const uint32_t aKh = smem_u32(Khi) + ((wx * 32 + l7 + l16h) * AQS + l8r) * 2;
    const uint32_t aKm = aKh + (64 * AQS) * 2;
    // V row-major [key][d]; trans-ldmatrix: rows = keys (l7+l8r), col = d (l16h)
    const uint32_t aVh = smem_u32(Vhi) + ((l7 + l8r) * AQS + wx * 48 + l16h) * 2;
    const uint32_t aVm = aVh + (64 * AQS) * 2;
    const uint32_t aPh = smem_u32(Phi) + ((wy * 16 + l7 + l8r) * APS + l16h) * 2;
    const uint32_t aPm = aPh + (64 * APS) * 2;

    // ---- cp.async loaders: 64 rows x 12 chunks of 16B per array ----
    const __nv_bfloat16* qsrcH = qh_ + (size_t)(bb * SEQ + qb * 64) * EMBED + qh * HD;
    const __nv_bfloat16* qsrcM = qm_ + (size_t)(bb * SEQ + qb * 64) * EMBED + qh * HD;
    const size_t kvbase = (size_t)(bb * NKV + kvh) * SEQ * HD;

    auto load_q = [&]() {
#pragma unroll
        for (int j = 0; j < 3; j++) {
            const int idx = tid + j * 256;
            const int r = idx / 12, c = idx % 12;
            cp16(&Qhi[r * AQS + c * 8], qsrcH + (size_t)r * EMBED + c * 8);
            cp16(&Qmi[r * AQS + c * 8], qsrcM + (size_t)r * EMBED + c * 8);
        }
    };
    auto load_k = [&](int kb) {
        const __nv_bfloat16* sh = kh_ + kvbase + (size_t)kb * 64 * HD;
        const __nv_bfloat16* sm2 = km_ + kvbase + (size_t)kb * 64 * HD;
#pragma unroll
        for (int j = 0; j < 3; j++) {
            const int idx = tid + j * 256;
            const int r = idx / 12, c = idx % 12;
            cp16(&Khi[r * AQS + c * 8], sh + r * HD + c * 8);
            cp16(&Kmi[r * AQS + c * 8], sm2 + r * HD + c * 8);
        }
    };
    auto load_v = [&](int kb) {
        const __nv_bfloat16* sh = vh_ + kvbase + (size_t)kb * 64 * HD;
        const __nv_bfloat16* sm2 = vm_ + kvbase + (size_t)kb * 64 * HD;
#pragma unroll
        for (int j = 0; j < 3; j++) {
            const int idx = tid + j * 256;
            const int r = idx / 12, c = idx % 12;
            cp16(&Vhi[r * AQS + c * 8], sh + r * HD + c * 8);
            cp16(&Vmi[r * AQS + c * 8], sm2 + r * HD + c * 8);
        }
    };

    load_q();
    load_k(0);
    CP_COMMIT();           // group: Q + K(0)
    load_v(0);
    CP_COMMIT();           // group: V(0)

    float accO[6][4];
#pragma unroll
    for (int nf = 0; nf < 6; nf++)
#pragma unroll
        for (int e = 0; e < 4; e++) accO[nf][e] = 0.0f;
    float m_run0 = -1e30f, m_run1 = -1e30f, l_run0 = 0.0f, l_run1 = 0.0f;

    for (int kb = 0; kb <= qb; kb++) {
        CP_WAIT1();            // Q+K(kb) complete (V(kb) may be in flight)
        __syncthreads();

        // ---- S = Q K^T ----
        float s[4][4];
#pragma unroll
        for (int nf = 0; nf < 4; nf++)
#pragma unroll
            for (int e = 0; e < 4; e++) s[nf][e] = 0.0f;

#pragma unroll
        for (int ks = 0; ks < 6; ks++) {
            const uint32_t ko = ks * 32;
            uint32_t ah[4], am[4];
            ldsm_x4(ah, aQh + ko);
            ldsm_x4(am, aQm + ko);
#pragma unroll
            for (int nfp = 0; nfp < 2; nfp++) {
                uint32_t bh[4], bm[4];
                ldsm_x4(bh, aKh + nfp * (16 * AQS * 2) + ko);
                ldsm_x4(bm, aKm + nfp * (16 * AQS * 2) + ko);
                const int n0f = nfp * 2, n1f = n0f + 1;
                mma_bf16(s[n0f], ah, bh);
                mma_bf16(s[n1f], ah, bh + 2);
                mma_bf16(s[n0f], am, bh);
                mma_bf16(s[n1f], am, bh + 2);
                mma_bf16(s[n0f], ah, bm);
                mma_bf16(s[n1f], ah, bm + 2);
            }
        }

        // ---- scale + causal mask + row max ----
        const int rowg0 = qb * 64 + r0, rowg1 = qb * 64 + r1;
#pragma unroll
        for (int nf = 0; nf < 4; nf++) {
            const int cg = kb * 64 + wx * 32 + nf * 8 + 2 * t4;
            s[nf][0] = (cg     > rowg0) ? -1e30f : s[nf][0] * scale;
            s[nf][1] = (cg + 1 > rowg0) ? -1e30f : s[nf][1] * scale;
            s[nf][2] = (cg     > rowg1) ? -1e30f : s[nf][2] * scale;
            s[nf][3] = (cg + 1 > rowg1) ? -1e30f : s[nf][3] * scale;
        }

        float mr0 = s[0][0], mr1 = s[0][2];
#pragma unroll
        for (int nf = 0; nf < 4; nf++) {
            mr0 = fmaxf(mr0, fmaxf(s[nf][0], s[nf][1]));
            mr1 = fmaxf(mr1, fmaxf(s[nf][2], s[nf][3]));
        }
        mr0 = fmaxf(mr0, __shfl_xor_sync(0xffffffffu, mr0, 1));
        mr0 = fmaxf(mr0, __shfl_xor_sync(0xffffffffu, mr0, 2));
        mr1 = fmaxf(mr1, __shfl_xor_sync(0xffffffffu, mr1, 1));
        mr1 = fmaxf(mr1, __shfl_xor_sync(0xffffffffu, mr1, 2));
        if (t4 == 0) {
            redM[wx * 64 + r0] = mr0;
            redM[wx * 64 + r1] = mr1;
        }
        __syncthreads();       // redM ready; all warps done reading K
        if (kb < qb) { load_k(kb + 1); CP_COMMIT(); }   // overwrite K safely

        mr0 = fmaxf(mr0, redM[(1 - wx) * 64 + r0]);
        mr1 = fmaxf(mr1, redM[(1 - wx) * 64 + r1]);

        const float mn0 = fmaxf(m_run0, mr0), mn1 = fmaxf(m_run1, mr1);
        const float co0 = __expf(m_run0 - mn0), co1 = __expf(m_run1 - mn1);
        m_run0 = mn0; m_run1 = mn1;

        float sum0 = 0.0f, sum1 = 0.0f;
#pragma unroll
        for (int nf = 0; nf < 4; nf++) {
            s[nf][0] = __expf(s[nf][0] - mn0);
            s[nf][1] = __expf(s[nf][1] - mn0);
            s[nf][2] = __expf(s[nf][2] - mn1);
            s[nf][3] = __expf(s[nf][3] - mn1);
            sum0 += s[nf][0] + s[nf][1];
            sum1 += s[nf][2] + s[nf][3];
            const int c = wx * 32 + nf * 8 + 2 * t4;
            uint32_t hw, mw;
            split2(s[nf][0], s[nf][1], hw, mw);
            *(uint32_t*)&Phi[r0 * APS + c] = hw;
            *(uint32_t*)&Pmi[r0 * APS + c] = mw;
            split2(s[nf][2], s[nf][3], hw, mw);
            *(uint32_t*)&Phi[r1 * APS + c] = hw;
            *(uint32_t*)&Pmi[r1 * APS + c] = mw;
        }
        sum0 += __shfl_xor_sync(0xffffffffu, sum0, 1);
        sum0 += __shfl_xor_sync(0xffffffffu, sum0, 2);
        sum1 += __shfl_xor_sync(0xffffffffu, sum1, 1);
        sum1 += __shfl_xor_sync(0xffffffffu, sum1, 2);
        if (t4 == 0) {
            redL[wx * 64 + r0] = sum0;
            redL[wx * 64 + r1] = sum1;
        }
        if (kb < qb) CP_WAIT1(); else CP_WAIT0();   // V(kb) complete
        __syncthreads();       // V + P + redL visible
        l_run0 = l_run0 * co0 + redL[r0] + redL[64 + r0];
        l_run1 = l_run1 * co1 + redL[r1] + redL[64 + r1];

        // ---- O = O*c + P V ----
#pragma unroll
        for (int nf = 0; nf < 6; nf++) {
            accO[nf][0] *= co0; accO[nf][1] *= co0;
            accO[nf][2] *= co1; accO[nf][3] *= co1;
        }
#pragma unroll
        for (int ks = 0; ks < 4; ks++) {
            const uint32_t kop = ks * 32;                 // P k-offset (bytes)
            const uint32_t kov = ks * (16 * AQS * 2);     // V key-row offset
            uint32_t ah[4], am[4];
            ldsm_x4(ah, aPh + kop);
            ldsm_x4(am, aPm + kop);
#pragma unroll
            for (int nfp = 0; nfp < 3; nfp++) {
                uint32_t bh[4], bm[4];
                ldsm_x4_t(bh, aVh + kov + nfp * 32);
                ldsm_x4_t(bm, aVm + kov + nfp * 32);
                const int n0f = nfp * 2, n1f = n0f + 1;
                mma_bf16(accO[n0f], ah, bh);
                mma_bf16(accO[n1f], ah, bh + 2);
                mma_bf16(accO[n0f], am, bh);
                mma_bf16(accO[n1f], am, bh + 2);
                mma_bf16(accO[n0f], ah, bm);
                mma_bf16(accO[n1f], ah, bm + 2);
            }
        }
        __syncthreads();       // all done reading V and P
        if (kb < qb) { load_v(kb + 1); CP_COMMIT(); }    // overwrite V safely
    }

    // ---- normalize and write pre-split O ----
    const float il0 = 1.0f / l_run0, il1 = 1.0f / l_run1;
    const size_t row0 = (size_t)(bb * SEQ + qb * 64 + r0);
    const size_t row1 = (size_t)(bb * SEQ + qb * 64 + r1);
#pragma unroll
    for (int nf = 0; nf < 6; nf++) {
        const int c = qh * HD + wx * 48 + nf * 8 + 2 * t4;
        uint32_t h, m;
        split2(accO[nf][0] * il0, accO[nf][1] * il0, h, m);
        *(uint32_t*)&outH[row0 * EMBED + c] = h;
        *(uint32_t*)&outM[row0 * EMBED + c] = m;
        split2(accO[nf][2] * il1, accO[nf][3] * il1, h, m);
        *(uint32_t*)&outH[row1 * EMBED + c] = h;
        *(uint32_t*)&outM[row1 * EMBED + c] = m;
    }
}

// ---------------------------------------------------------------------------
// Launch
// ---------------------------------------------------------------------------
extern "C" void kernel_launch(void* const* d_in, const int* in_sizes, int n_in,
                              void* d_out, int out_size)
{
    const float* x         = (const float*)d_in[0];
    const int*   positions = (const int*)d_in[1];
    const float* W_qkv     = (const float*)d_in[3];
    const float* W_o       = (const float*)d_in[4];
    float* out = (float*)d_out;

    float* qkv;  cudaGetSymbolAddress((void**)&qkv,  g_qkv);
    __nv_bfloat16 *xh, *xm, *wqh, *wqm, *woh, *wom, *ah, *am;
    __nv_bfloat16 *qsh, *qsm, *ksh, *ksm, *vsh, *vsm;
    cudaGetSymbolAddress((void**)&xh,  g_xh);   cudaGetSymbolAddress((void**)&xm,  g_xm);
    cudaGetSymbolAddress((void**)&wqh, g_wqh);  cudaGetSymbolAddress((void**)&wqm, g_wqm);
    cudaGetSymbolAddress((void**)&woh, g_woh);  cudaGetSymbolAddress((void**)&wom, g_wom);
    cudaGetSymbolAddress((void**)&ah,  g_ah);   cudaGetSymbolAddress((void**)&am,  g_am);
    cudaGetSymbolAddress((void**)&qsh, g_qsh);  cudaGetSymbolAddress((void**)&qsm, g_qsm);
    cudaGetSymbolAddress((void**)&ksh, g_ksh);  cudaGetSymbolAddress((void**)&ksm, g_ksm);
    cudaGetSymbolAddress((void**)&vsh, g_vsh);  cudaGetSymbolAddress((void**)&vsm, g_vsm);

    cudaFuncSetAttribute(attn_mma, cudaFuncAttributeMaxDynamicSharedMemorySize,
                         ATTN_SM_BYTES);
    cudaFuncSetAttribute(gemm_pre, cudaFuncAttributeMaxDynamicSharedMemorySize,
                         GEMM_SMEM_BYTES);

    // 0) pre-split inputs/weights
    {
        int n4;
        n4 = ROWS * EMBED / 4;
        split_kernel<<<(n4 + 255) / 256, 256>>>(x, xh, xm, n4);
        n4 = QKV_N * EMBED / 4;
        split_kernel<<<(n4 + 255) / 256, 256>>>(W_qkv, wqh, wqm, n4);
        n4 = EMBED * EMBED / 4;
        split_kernel<<<(n4 + 255) / 256, 256>>>(W_o, woh, wom, n4);
    }

    // 1) QKV projection
    gemm_pre<<<dim3(QKV_N / 128, ROWS / 128), 256, GEMM_SMEM_BYTES>>>(
        xh, xm, wqh, wqm, qkv, ROWS, QKV_N, EMBED);

    // 2) RoPE + pre-split Q,K ; pre-split V
    {
        const int totqk = ROWS * (NQ + NKV) * (HD / 2);
        rope_split_qk<<<(totqk + 255) / 256, 256>>>(qkv, positions, qsh, qsm, ksh, ksm);
        const int totv = ROWS * NKV * (HD / 4);
        split_v<<<(totv + 255) / 256, 256>>>(qkv, vsh, vsm);
    }

    // 3) Causal GQA attention -> pre-split O
    attn_mma<<<dim3(SEQ / 64, NQ, BATCH), 256, ATTN_SM_BYTES>>>(
        qsh, qsm, ksh, ksm, vsh, vsm, ah, am);

    // 4) Output projection
    gemm_pre<<<dim3(EMBED / 128, ROWS / 128), 256, GEMM_SMEM_BYTES>>>(
        ah, am, woh, wom, out, ROWS, EMBED, EMBED);
}

// round 14
// speedup vs baseline: 1.3353x; 1.0170x over previous
#include <cuda_runtime.h>
#include <cuda_bf16.h>
#include <math.h>
#include <stdint.h>

#define EMBED 3072
#define NQ 32
#define NKV 8
#define HD 96
#define BATCH 2
#define SEQ 2048
#define ROWS (BATCH*SEQ)                 // 4096
#define QKV_N (NQ*HD + 2*NKV*HD)         // 4608
#define KOFF (NQ*HD)                     // 3072
#define VOFF (NQ*HD + NKV*HD)            // 3840

// Scratch (allocation-free rule: __device__ globals)
__device__ float g_qkv[ROWS * QKV_N];
__device__ __nv_bfloat16 g_xh[ROWS * EMBED],   g_xm[ROWS * EMBED];
__device__ __nv_bfloat16 g_wqh[QKV_N * EMBED], g_wqm[QKV_N * EMBED];
__device__ __nv_bfloat16 g_woh[EMBED * EMBED], g_wom[EMBED * EMBED];
__device__ __nv_bfloat16 g_ah[ROWS * EMBED],   g_am[ROWS * EMBED];   // attn out (pre-split)
// pre-split attention operands
__device__ __nv_bfloat16 g_qsh[ROWS * EMBED],  g_qsm[ROWS * EMBED];  // Q post-rope
__device__ __nv_bfloat16 g_ksh[BATCH*NKV*SEQ*HD], g_ksm[BATCH*NKV*SEQ*HD];
__device__ __nv_bfloat16 g_vsh[BATCH*NKV*SEQ*HD], g_vsm[BATCH*NKV*SEQ*HD];

// ---------------------------------------------------------------------------
// Helpers
// ---------------------------------------------------------------------------
__device__ __forceinline__ uint32_t smem_u32(const void* p) {
    return (uint32_t)__cvta_generic_to_shared(p);
}

__device__ __forceinline__ void mma_bf16(float* d, const uint32_t* a, const uint32_t* b) {
    asm volatile(
        "mma.sync.aligned.m16n8k16.row.col.f32.bf16.bf16.f32 "
        "{%0,%1,%2,%3}, {%4,%5,%6,%7}, {%8,%9}, {%0,%1,%2,%3};"
        : "+f"(d[0]), "+f"(d[1]), "+f"(d[2]), "+f"(d[3])
        : "r"(a[0]), "r"(a[1]), "r"(a[2]), "r"(a[3]), "r"(b[0]), "r"(b[1]));
}

__device__ __forceinline__ void ldsm_x4(uint32_t* r, uint32_t addr) {
    asm volatile("ldmatrix.sync.aligned.m8n8.x4.shared.b16 {%0,%1,%2,%3}, [%4];"
                 : "=r"(r[0]), "=r"(r[1]), "=r"(r[2]), "=r"(r[3]) : "r"(addr));
}

__device__ __forceinline__ void ldsm_x4_t(uint32_t* r, uint32_t addr) {
    asm volatile("ldmatrix.sync.aligned.m8n8.x4.trans.shared.b16 {%0,%1,%2,%3}, [%4];"
                 : "=r"(r[0]), "=r"(r[1]), "=r"(r[2]), "=r"(r[3]) : "r"(addr));
}

__device__ __forceinline__ void split2(float x, float y, uint32_t& hi, uint32_t& mid) {
    __nv_bfloat16 hx = __float2bfloat16(x);
    __nv_bfloat16 hy = __float2bfloat16(y);
    __nv_bfloat16 mx = __float2bfloat16(x - __bfloat162float(hx));
    __nv_bfloat16 my = __float2bfloat16(y - __bfloat162float(hy));
    hi  = ((uint32_t)__bfloat16_as_ushort(hy) << 16) | __bfloat16_as_ushort(hx);
    mid = ((uint32_t)__bfloat16_as_ushort(my) << 16) | __bfloat16_as_ushort(mx);
}

__device__ __forceinline__ void split1(float x, __nv_bfloat16& h, __nv_bfloat16& m) {
    h = __float2bfloat16(x);
    m = __float2bfloat16(x - __bfloat162float(h));
}

__device__ __forceinline__ void cp16(void* smem_ptr, const void* gmem_ptr) {
    uint32_t s = smem_u32(smem_ptr);
    asm volatile("cp.async.cg.shared.global [%0], [%1], 16;\n" :: "r"(s), "l"(gmem_ptr));
}
#define CP_COMMIT() asm volatile("cp.async.commit_group;\n" ::: "memory")
#define CP_WAIT0()  asm volatile("cp.async.wait_group 0;\n" ::: "memory")
#define CP_WAIT1()  asm volatile("cp.async.wait_group 1;\n" ::: "memory")

// ---------------------------------------------------------------------------
// fp32 -> bf16 hi/mid split (elementwise)
// ---------------------------------------------------------------------------
__global__ void split_kernel(const float* __restrict__ src,
                             __nv_bfloat16* __restrict__ hi,
                             __nv_bfloat16* __restrict__ mid, int n4)
{
    int i = blockIdx.x * blockDim.x + threadIdx.x;
    if (i >= n4) return;
    float4 v = ((const float4*)src)[i];
    uint2 h, m;
    split2(v.x, v.y, h.x, m.x);
    split2(v.z, v.w, h.y, m.y);
    ((uint2*)hi)[i]  = h;
    ((uint2*)mid)[i] = m;
}

// ---------------------------------------------------------------------------
// Fused RoPE + split for Q (heads 0..31) and K (heads 32..39).
// ---------------------------------------------------------------------------
__global__ void rope_split_qk(const float* __restrict__ qkv,
                              const int* __restrict__ positions,
                              __nv_bfloat16* __restrict__ qh_, __nv_bfloat16* __restrict__ qm_,
                              __nv_bfloat16* __restrict__ kh_, __nv_bfloat16* __restrict__ km_)
{
    const int total = ROWS * (NQ + NKV) * (HD / 2);
    int idx = blockIdx.x * blockDim.x + threadIdx.x;
    if (idx >= total) return;

    const int i   = idx % (HD / 2);
    const int h   = (idx / (HD / 2)) % (NQ + NKV);
    const int row = idx / ((HD / 2) * (NQ + NKV));

    const int pos = positions[row & (SEQ - 1)];
    const float e = (float)(2 * i) / (float)HD;
    const float inv_freq = expf(-e * 9.210340371976184f);
    const float ang = (float)pos * inv_freq;
    float s, c;
    sincosf(ang, &s, &c);

    const float* base = qkv + (size_t)row * QKV_N + h * HD + i;
    const float t1 = base[0];
    const float t2 = base[HD / 2];
    const float o1 = t1 * c - t2 * s;
    const float o2 = t2 * c + t1 * s;

    __nv_bfloat16 h1, m1, h2, m2;
    split1(o1, h1, m1);
    split1(o2, h2, m2);

    if (h < NQ) {
        const size_t b = (size_t)row * EMBED + h * HD + i;
        qh_[b] = h1; qm_[b] = m1;
        qh_[b + HD/2] = h2; qm_[b + HD/2] = m2;
    } else {
        const int kvh = h - NQ;
        const int bb = row >> 11, ss = row & (SEQ - 1);
        const size_t b = ((size_t)(bb * NKV + kvh) * SEQ + ss) * HD + i;
        kh_[b] = h1; km_[b] = m1;
        kh_[b + HD/2] = h2; km_[b + HD/2] = m2;
    }
}

// ---------------------------------------------------------------------------
// V split (no rope, row-major [(bb*8+kvh)*2048+s][96]).
// ---------------------------------------------------------------------------
__global__ void split_v(const float* __restrict__ qkv,
                        __nv_bfloat16* __restrict__ vh_, __nv_bfloat16* __restrict__ vm_)
{
    const int total = ROWS * NKV * (HD / 4);
    int idx = blockIdx.x * blockDim.x + threadIdx.x;
    if (idx >= total) return;
    const int d4  = idx % (HD / 4);
    const int kvh = (idx / (HD / 4)) % NKV;
    const int row = idx / ((HD / 4) * NKV);
    const int bb = row >> 11, ss = row & (SEQ - 1);

    float4 v = *(const float4*)(qkv + (size_t)row * QKV_N + VOFF + kvh * HD + d4 * 4);
    uint2 h, m;
    split2(v.x, v.y, h.x, m.x);
    split2(v.z, v.w, h.y, m.y);
    const size_t b = ((size_t)(bb * NKV + kvh) * SEQ + ss) * HD + d4 * 4;
    *(uint2*)&vh_[b] = h;
    *(uint2*)&vm_[b] = m;
}

// ---------------------------------------------------------------------------
// Pre-split bf16 GEMM, cp.async double-buffered, ldmatrix + fragment
// double-buffering (B prefetched one nfp ahead to hide LDSM->MMA latency).
// ---------------------------------------------------------------------------
#define BM 128
#define BN 128
#define BK 32
#define SB 40
#define ARR (128 * SB)
#define STG (4 * ARR)
#define GEMM_SMEM_BYTES (2 * STG * 2)

__global__ __launch_bounds__(256, 2) void gemm_pre(const __nv_bfloat16* __restrict__ Ah,
                                                   const __nv_bfloat16* __restrict__ Am,
                                                   const __nv_bfloat16* __restrict__ Bh,
                                                   const __nv_bfloat16* __restrict__ Bm,
                                                   float* __restrict__ C,
                                                   int M, int N, int K)
{
    extern __shared__ __nv_bfloat16 smem[];

    const int tid  = threadIdx.x;
    const int warp = tid >> 5;
    const int lane = tid & 31;
    const int m0 = blockIdx.y * BM;
    const int n0 = blockIdx.x * BN;

    const int wm = (warp >> 1) * 32;
    const int wn = (warp & 1) * 64;
    const int g  = lane >> 2;
    const int t4 = lane & 3;

    const int l7   = lane & 7;
    const int l8r  = lane & 8;
    const int l16h = (lane & 16) >> 1;

    const int lrow = tid >> 1;
    const int lco  = (tid & 1) * 16;

    float acc[2][8][4];
#pragma unroll
    for (int mf = 0; mf < 2; mf++)
#pragma unroll
        for (int nf = 0; nf < 8; nf++)
#pragma unroll
            for (int r = 0; r < 4; r++) acc[mf][nf][r] = 0.0f;

    const size_t arow = (size_t)(m0 + lrow) * K;
    const size_t brow = (size_t)(n0 + lrow) * K;

    auto load_tile = [&](int k0, int stage) {
        __nv_bfloat16* s = smem + stage * STG;
        const int so = lrow * SB + lco;
        cp16(&s[so],             Ah + arow + k0 + lco);
        cp16(&s[so + 8],         Ah + arow + k0 + lco + 8);
        cp16(&s[ARR + so],       Am + arow + k0 + lco);
        cp16(&s[ARR + so + 8],   Am + arow + k0 + lco + 8);
        cp16(&s[2*ARR + so],     Bh + brow + k0 + lco);
        cp16(&s[2*ARR + so + 8], Bh + brow + k0 + lco + 8);
        cp16(&s[3*ARR + so],     Bm + brow + k0 + lco);
        cp16(&s[3*ARR + so + 8], Bm + brow + k0 + lco + 8);
    };

    const int T = K / BK;
    load_tile(0, 0);
    CP_COMMIT();

    for (int t = 0; t < T; t++) {
        CP_WAIT0();
        __syncthreads();   // orders prev-iter reads of target stage before overwrite
        if (t + 1 < T) {
            load_tile((t + 1) * BK, (t + 1) & 1);
            CP_COMMIT();
        }

        const __nv_bfloat16* base = smem + (t & 1) * STG;
        const uint32_t aAh = smem_u32(base) + ((wm + l7 + l8r) * SB + l16h) * 2;
        const uint32_t aAm = aAh + ARR * 2;
        const uint32_t aBh = smem_u32(base) + (2 * ARR + (wn + l7 + l16h) * SB + l8r) * 2;
        const uint32_t aBm = aBh + ARR * 2;

#pragma unroll
        for (int ks = 0; ks < 2; ks++) {
            const uint32_t ko = ks * 32;

            uint32_t ahi[2][4], ami[2][4];
            ldsm_x4(ahi[0], aAh + ko);
            ldsm_x4(ahi[1], aAh + (16 * SB * 2) + ko);
            ldsm_x4(ami[0], aAm + ko);
            ldsm_x4(ami[1], aAm + (16 * SB * 2) + ko);

            // B fragment double buffer: prefetch nfp+1 before MMAs of nfp
            uint32_t bh[2][4], bm[2][4];
            ldsm_x4(bh[0], aBh + ko);
            ldsm_x4(bm[0], aBm + ko);

#pragma unroll
            for (int nfp = 0; nfp < 4; nfp++) {
                const int cur = nfp & 1, nxt = cur ^ 1;
                if (nfp < 3) {
                    ldsm_x4(bh[nxt], aBh + (nfp + 1) * (16 * SB * 2) + ko);
                    ldsm_x4(bm[nxt], aBm + (nfp + 1) * (16 * SB * 2) + ko);
                }
                const int n0f = nfp * 2, n1f = n0f + 1;
                mma_bf16(acc[0][n0f], ahi[0], bh[cur]);
                mma_bf16(acc[1][n0f], ahi[1], bh[cur]);
                mma_bf16(acc[0][n1f], ahi[0], bh[cur] + 2);
                mma_bf16(acc[1][n1f], ahi[1], bh[cur] + 2);
                mma_bf16(acc[0][n0f], ami[0], bh[cur]);
                mma_bf16(acc[1][n0f], ami[1], bh[cur]);
                mma_bf16(acc[0][n1f], ami[0], bh[cur] + 2);
                mma_bf16(acc[1][n1f], ami[1], bh[cur] + 2);
                mma_bf16(acc[0][n0f], ahi[0], bm[cur]);
                mma_bf16(acc[1][n0f], ahi[1], bm[cur]);
                mma_bf16(acc[0][n1f], ahi[0], bm[cur] + 2);
                mma_bf16(acc[1][n1f], ahi[1], bm[cur] + 2);
            }
        }
        // no trailing barrier: next iteration's wait+sync provides WAR ordering
    }

#pragma unroll
    for (int mf = 0; mf < 2; mf++) {
#pragma unroll
        for (int nf = 0; nf < 8; nf++) {
            const int r = m0 + wm + mf * 16 + g;
            const int c = n0 + wn + nf * 8 + 2 * t4;
            float2 v0 = {acc[mf][nf][0], acc[mf][nf][1]};
            float2 v1 = {acc[mf][nf][2], acc[mf][nf][3]};
            *(float2*)(C + (size_t)r * N + c)       = v0;
            *(float2*)(C + (size_t)(r + 8) * N + c) = v1;
        }
    }
}

// ---------------------------------------------------------------------------
// Causal GQA flash attention (unchanged from R12).
// ---------------------------------------------------------------------------
#define AQS 104
#define APS 72
#define ATTN_SM_BYTES ((6*64*AQS + 2*64*APS) * 2 + 2 * 128 * 4)   // 99,328 B

__global__ __launch_bounds__(256, 2) void attn_mma(
    const __nv_bfloat16* __restrict__ qh_, const __nv_bfloat16* __restrict__ qm_,
    const __nv_bfloat16* __restrict__ kh_, const __nv_bfloat16* __restrict__ km_,
    const __nv_bfloat16* __restrict__ vh_, const __nv_bfloat16* __restrict__ vm_,
    __nv_bfloat16* __restrict__ outH, __nv_bfloat16* __restrict__ outM)
{
    extern __shared__ char sm_raw[];
    __nv_bfloat16* Qhi = (__nv_bfloat16*)sm_raw;
    __nv_bfloat16* Qmi = Qhi + 64 * AQS;
    __nv_bfloat16* Khi = Qmi + 64 * AQS;
    __nv_bfloat16* Kmi = Khi + 64 * AQS;
    __nv_bfloat16* Vhi = Kmi + 64 * AQS;
    __nv_bfloat16* Vmi = Vhi + 64 * AQS;
    __nv_bfloat16* Phi = Vmi + 64 * AQS;
    __nv_bfloat16* Pmi = Phi + 64 * APS;
    float* redM = (float*)(Pmi + 64 * APS);
    float* redL = redM + 128;

    const int qb = blockIdx.x;
    const int qh = blockIdx.y;
    const int bb = blockIdx.z;
    const int kvh = qh >> 2;
    const int tid = threadIdx.x, warp = tid >> 5, lane = tid & 31;
    const int wy = warp >> 1, wx = warp & 1;
    const int g = lane >> 2, t4 = lane & 3;
    const int r0 = wy * 16 + g, r1 = r0 + 8;
    const float scale = 0.10206207261596577f;

    const int l7   = lane & 7;
    const int l8r  = lane & 8;
    const int l16h = (lane & 16) >> 1;

    const uint32_t aQh = smem_u32(Qhi) + ((wy * 16 + l7 + l8r) * AQS + l16h) * 2;
    const uint32_t aQm = aQh + (64 * AQS) * 2;
    const uint32_t aKh = smem_u32(Khi) + ((wx * 32 + l7 + l16h) * AQS + l8r) * 2;
    const uint32_t aKm = aKh + (64 * AQS) * 2;
    const uint32_t aVh = smem_u32(Vhi) + ((l7 + l8r) * AQS + wx * 48 + l16h) * 2;
    const uint32_t aVm = aVh + (64 * AQS) * 2;
    const uint32_t aPh = smem_u32(Phi) + ((wy * 16 + l7 + l8r) * APS + l16h) * 2;
    const uint32_t aPm = aPh + (64 * APS) * 2;

    const __nv_bfloat16* qsrcH = qh_ + (size_t)(bb * SEQ + qb * 64) * EMBED + qh * HD;
    const __nv_bfloat16* qsrcM = qm_ + (size_t)(bb * SEQ + qb * 64) * EMBED + qh * HD;
    const size_t kvbase = (size_t)(bb * NKV + kvh) * SEQ * HD;

    auto load_q = [&]() {
#pragma unroll
        for (int j = 0; j < 3; j++) {
            const int idx = tid + j * 256;
            const int r = idx / 12, c = idx % 12;
            cp16(&Qhi[r * AQS + c * 8], qsrcH + (size_t)r * EMBED + c * 8);
            cp16(&Qmi[r * AQS + c * 8], qsrcM + (size_t)r * EMBED + c * 8);
        }
    };
    auto load_k = [&](int kb) {
        const __nv_bfloat16* sh = kh_ + kvbase + (size_t)kb * 64 * HD;
        const __nv_bfloat16* sm2 = km_ + kvbase + (size_t)kb * 64 * HD;
#pragma unroll
        for (int j = 0; j < 3; j++) {
            const int idx = tid + j * 256;
            const int r = idx / 12, c = idx % 12;
            cp16(&Khi[r * AQS + c * 8], sh + r * HD + c * 8);
            cp16(&Kmi[r * AQS + c * 8], sm2 + r * HD + c * 8);
        }
    };
    auto load_v = [&](int kb) {
        const __nv_bfloat16* sh = vh_ + kvbase + (size_t)kb * 64 * HD;
        const __nv_bfloat16* sm2 = vm_ + kvbase + (size_t)kb * 64 * HD;
#pragma unroll
        for (int j = 0; j < 3; j++) {
            const int idx = tid + j * 256;
            const int r = idx / 12, c = idx % 12;
            cp16(&Vhi[r * AQS + c * 8], sh + r * HD + c * 8);
            cp16(&Vmi[r * AQS + c * 8], sm2 + r * HD + c * 8);
        }
    };

    load_q();
    load_k(0);
    CP_COMMIT();
    load_v(0);
    CP_COMMIT();

    float accO[6][4];
#pragma unroll
    for (int nf = 0; nf < 6; nf++)
#pragma unroll
        for (int e = 0; e < 4; e++) accO[nf][e] = 0.0f;
    float m_run0 = -1e30f, m_run1 = -1e30f, l_run0 = 0.0f, l_run1 = 0.0f;

    for (int kb = 0; kb <= qb; kb++) {
        CP_WAIT1();
        __syncthreads();

        float s[4][4];
#pragma unroll
        for (int nf = 0; nf < 4; nf++)
#pragma unroll
            for (int e = 0; e < 4; e++) s[nf][e] = 0.0f;

#pragma unroll
        for (int ks = 0; ks < 6; ks++) {
            const uint32_t ko = ks * 32;
            uint32_t ah[4], am[4];
            ldsm_x4(ah, aQh + ko);
            ldsm_x4(am, aQm + ko);
#pragma unroll
            for (int nfp = 0; nfp < 2; nfp++) {
                uint32_t bh[4], bm[4];
                ldsm_x4(bh, aKh + nfp * (16 * AQS * 2) + ko);
                ldsm_x4(bm, aKm + nfp * (16 * AQS * 2) + ko);
                const int n0f = nfp * 2, n1f = n0f + 1;
                mma_bf16(s[n0f], ah, bh);
                mma_bf16(s[n1f], ah, bh + 2);
                mma_bf16(s[n0f], am, bh);
                mma_bf16(s[n1f], am, bh + 2);
                mma_bf16(s[n0f], ah, bm);
                mma_bf16(s[n1f], ah, bm + 2);
            }
        }

        const int rowg0 = qb * 64 + r0, rowg1 = qb * 64 + r1;
#pragma unroll
        for (int nf = 0; nf < 4; nf++) {
            const int cg = kb * 64 + wx * 32 + nf * 8 + 2 * t4;
            s[nf][0] = (cg     > rowg0) ? -1e30f : s[nf][0] * scale;
            s[nf][1] = (cg + 1 > rowg0) ? -1e30f : s[nf][1] * scale;
            s[nf][2] = (cg     > rowg1) ? -1e30f : s[nf][2] * scale;
            s[nf][3] = (cg + 1 > rowg1) ? -1e30f : s[nf][3] * scale;
        }

        float mr0 = s[0][0], mr1 = s[0][2];
#pragma unroll
        for (int nf = 0; nf < 4; nf++) {
            mr0 = fmaxf(mr0, fmaxf(s[nf][0], s[nf][1]));
            mr1 = fmaxf(mr1, fmaxf(s[nf][2], s[nf][3]));
        }
        mr0 = fmaxf(mr0, __shfl_xor_sync(0xffffffffu, mr0, 1));
        mr0 = fmaxf(mr0, __shfl_xor_sync(0xffffffffu, mr0, 2));
        mr1 = fmaxf(mr1, __shfl_xor_sync(0xffffffffu, mr1, 1));
        mr1 = fmaxf(mr1, __shfl_xor_sync(0xffffffffu, mr1, 2));
        if (t4 == 0) {
            redM[wx * 64 + r0] = mr0;
            redM[wx * 64 + r1] = mr1;
        }
        __syncthreads();
        if (kb < qb) { load_k(kb + 1); CP_COMMIT(); }

        mr0 = fmaxf(mr0, redM[(1 - wx) * 64 + r0]);
        mr1 = fmaxf(mr1, redM[(1 - wx) * 64 + r1]);

        const float mn0 = fmaxf(m_run0, mr0), mn1 = fmaxf(m_run1, mr1);
        const float co0 = __expf(m_run0 - mn0), co1 = __expf(m_run1 - mn1);
        m_run0 = mn0; m_run1 = mn1;

        float sum0 = 0.0f, sum1 = 0.0f;
#pragma unroll
        for (int nf = 0; nf < 4; nf++) {
            s[nf][0] = __expf(s[nf][0] - mn0);
            s[nf][1] = __expf(s[nf][1] - mn0);
            s[nf][2] = __expf(s[nf][2] - mn1);
            s[nf][3] = __expf(s[nf][3] - mn1);
            sum0 += s[nf][0] + s[nf][1];
            sum1 += s[nf][2] + s[nf][3];
            const int c = wx * 32 + nf * 8 + 2 * t4;
            uint32_t hw, mw;
            split2(s[nf][0], s[nf][1], hw, mw);
            *(uint32_t*)&Phi[r0 * APS + c] = hw;
            *(uint32_t*)&Pmi[r0 * APS + c] = mw;
            split2(s[nf][2], s[nf][3], hw, mw);
            *(uint32_t*)&Phi[r1 * APS + c] = hw;
            *(uint32_t*)&Pmi[r1 * APS + c] = mw;
        }
        sum0 += __shfl_xor_sync(0xffffffffu, sum0, 1);
        sum0 += __shfl_xor_sync(0xffffffffu, sum0, 2);
        sum1 += __shfl_xor_sync(0xffffffffu, sum1, 1);
        sum1 += __shfl_xor_sync(0xffffffffu, sum1, 2);
        if (t4 == 0) {
            redL[wx * 64 + r0] = sum0;
            redL[wx * 64 + r1] = sum1;
        }
        if (kb < qb) CP_WAIT1(); else CP_WAIT0();
        __syncthreads();
        l_run0 = l_run0 * co0 + redL[r0] + redL[64 + r0];
        l_run1 = l_run1 * co1 + redL[r1] + redL[64 + r1];

#pragma unroll
        for (int nf = 0; nf < 6; nf++) {
            accO[nf][0] *= co0; accO[nf][1] *= co0;
            accO[nf][2] *= co1; accO[nf][3] *= co1;
        }
#pragma unroll
        for (int ks = 0; ks < 4; ks++) {
            const uint32_t kop = ks * 32;
            const uint32_t kov = ks * (16 * AQS * 2);
            uint32_t ah[4], am[4];
            ldsm_x4(ah, aPh + kop);
            ldsm_x4(am, aPm + kop);
#pragma unroll
            for (int nfp = 0; nfp < 3; nfp++) {
                uint32_t bh[4], bm[4];
                ldsm_x4_t(bh, aVh + kov + nfp * 32);
                ldsm_x4_t(bm, aVm + kov + nfp * 32);
                const int n0f = nfp * 2, n1f = n0f + 1;
                mma_bf16(accO[n0f], ah, bh);
                mma_bf16(accO[n1f], ah, bh + 2);
                mma_bf16(accO[n0f], am, bh);
                mma_bf16(accO[n1f], am, bh + 2);
                mma_bf16(accO[n0f], ah, bm);
                mma_bf16(accO[n1f], ah, bm + 2);
            }
        }
        __syncthreads();
        if (kb < qb) { load_v(kb + 1); CP_COMMIT(); }
    }

    const float il0 = 1.0f / l_run0, il1 = 1.0f / l_run1;
    const size_t row0 = (size_t)(bb * SEQ + qb * 64 + r0);
    const size_t row1 = (size_t)(bb * SEQ + qb * 64 + r1);
#pragma unroll
    for (int nf = 0; nf < 6; nf++) {
        const int c = qh * HD + wx * 48 + nf * 8 + 2 * t4;
        uint32_t h, m;
        split2(accO[nf][0] * il0, accO[nf][1] * il0, h, m);
        *(uint32_t*)&outH[row0 * EMBED + c] = h;
        *(uint32_t*)&outM[row0 * EMBED + c] = m;
        split2(accO[nf][2] * il1, accO[nf][3] * il1, h, m);
        *(uint32_t*)&outH[row1 * EMBED + c] = h;
        *(uint32_t*)&outM[row1 * EMBED + c] = m;
    }
}

// ---------------------------------------------------------------------------
// Launch
// ---------------------------------------------------------------------------
extern "C" void kernel_launch(void* const* d_in, const int* in_sizes, int n_in,
                              void* d_out, int out_size)
{
    const float* x         = (const float*)d_in[0];
    const int*   positions = (const int*)d_in[1];
    const float* W_qkv     = (const float*)d_in[3];
    const float* W_o       = (const float*)d_in[4];
    float* out = (float*)d_out;

    float* qkv;  cudaGetSymbolAddress((void**)&qkv,  g_qkv);
    __nv_bfloat16 *xh, *xm, *wqh, *wqm, *woh, *wom, *ah, *am;
    __nv_bfloat16 *qsh, *qsm, *ksh, *ksm, *vsh, *vsm;
    cudaGetSymbolAddress((void**)&xh,  g_xh);   cudaGetSymbolAddress((void**)&xm,  g_xm);
    cudaGetSymbolAddress((void**)&wqh, g_wqh);  cudaGetSymbolAddress((void**)&wqm, g_wqm);
    cudaGetSymbolAddress((void**)&woh, g_woh);  cudaGetSymbolAddress((void**)&wom, g_wom);
    cudaGetSymbolAddress((void**)&ah,  g_ah);   cudaGetSymbolAddress((void**)&am,  g_am);
    cudaGetSymbolAddress((void**)&qsh, g_qsh);  cudaGetSymbolAddress((void**)&qsm, g_qsm);
    cudaGetSymbolAddress((void**)&ksh, g_ksh);  cudaGetSymbolAddress((void**)&ksm, g_ksm);
    cudaGetSymbolAddress((void**)&vsh, g_vsh);  cudaGetSymbolAddress((void**)&vsm, g_vsm);

    cudaFuncSetAttribute(attn_mma, cudaFuncAttributeMaxDynamicSharedMemorySize,
                         ATTN_SM_BYTES);
    cudaFuncSetAttribute(gemm_pre, cudaFuncAttributeMaxDynamicSharedMemorySize,
                         GEMM_SMEM_BYTES);

    // 0) pre-split inputs/weights
    {
        int n4;
        n4 = ROWS * EMBED / 4;
        split_kernel<<<(n4 + 255) / 256, 256>>>(x, xh, xm, n4);
        n4 = QKV_N * EMBED / 4;
        split_kernel<<<(n4 + 255) / 256, 256>>>(W_qkv, wqh, wqm, n4);
        n4 = EMBED * EMBED / 4;
        split_kernel<<<(n4 + 255) / 256, 256>>>(W_o, woh, wom, n4);
    }

    // 1) QKV projection
    gemm_pre<<<dim3(QKV_N / 128, ROWS / 128), 256, GEMM_SMEM_BYTES>>>(
        xh, xm, wqh, wqm, qkv, ROWS, QKV_N, EMBED);

    // 2) RoPE + pre-split Q,K ; pre-split V
    {
        const int totqk = ROWS * (NQ + NKV) * (HD / 2);
        rope_split_qk<<<(totqk + 255) / 256, 256>>>(qkv, positions, qsh, qsm, ksh, ksm);
        const int totv = ROWS * NKV * (HD / 4);
        split_v<<<(totv + 255) / 256, 256>>>(qkv, vsh, vsm);
    }

    // 3) Causal GQA attention -> pre-split O
    attn_mma<<<dim3(SEQ / 64, NQ, BATCH), 256, ATTN_SM_BYTES>>>(
        qsh, qsm, ksh, ksm, vsh, vsm, ah, am);

    // 4) Output projection
    gemm_pre<<<dim3(EMBED / 128, ROWS / 128), 256, GEMM_SMEM_BYTES>>>(
        ah, am, woh, wom, out, ROWS, EMBED, EMBED);
}

// round 15
// speedup vs baseline: 1.3659x; 1.0229x over previous
#include <cuda_runtime.h>
#include <cuda_bf16.h>
#include <math.h>
#include <stdint.h>

#define EMBED 3072
#define NQ 32
#define NKV 8
#define HD 96
#define BATCH 2
#define SEQ 2048
#define ROWS (BATCH*SEQ)                 // 4096
#define QKV_N (NQ*HD + 2*NKV*HD)         // 4608
#define KOFF (NQ*HD)                     // 3072
#define VOFF (NQ*HD + NKV*HD)            // 3840

// Scratch (allocation-free rule: __device__ globals)
__device__ float g_qkv[ROWS * QKV_N];
__device__ __nv_bfloat16 g_xh[ROWS * EMBED],   g_xm[ROWS * EMBED];
__device__ __nv_bfloat16 g_wqh[QKV_N * EMBED], g_wqm[QKV_N * EMBED];
__device__ __nv_bfloat16 g_woh[EMBED * EMBED], g_wom[EMBED * EMBED];
__device__ __nv_bfloat16 g_ah[ROWS * EMBED],   g_am[ROWS * EMBED];   // attn out (pre-split)
// pre-split attention operands
__device__ __nv_bfloat16 g_qsh[ROWS * EMBED],  g_qsm[ROWS * EMBED];  // Q post-rope
__device__ __nv_bfloat16 g_ksh[BATCH*NKV*SEQ*HD], g_ksm[BATCH*NKV*SEQ*HD];
__device__ __nv_bfloat16 g_vsh[BATCH*NKV*SEQ*HD], g_vsm[BATCH*NKV*SEQ*HD];

// ---------------------------------------------------------------------------
// Helpers
// ---------------------------------------------------------------------------
__device__ __forceinline__ uint32_t smem_u32(const void* p) {
    return (uint32_t)__cvta_generic_to_shared(p);
}

__device__ __forceinline__ void mma_bf16(float* d, const uint32_t* a, const uint32_t* b) {
    asm volatile(
        "mma.sync.aligned.m16n8k16.row.col.f32.bf16.bf16.f32 "
        "{%0,%1,%2,%3}, {%4,%5,%6,%7}, {%8,%9}, {%0,%1,%2,%3};"
        : "+f"(d[0]), "+f"(d[1]), "+f"(d[2]), "+f"(d[3])
        : "r"(a[0]), "r"(a[1]), "r"(a[2]), "r"(a[3]), "r"(b[0]), "r"(b[1]));
}

__device__ __forceinline__ void ldsm_x4(uint32_t* r, uint32_t addr) {
    asm volatile("ldmatrix.sync.aligned.m8n8.x4.shared.b16 {%0,%1,%2,%3}, [%4];"
                 : "=r"(r[0]), "=r"(r[1]), "=r"(r[2]), "=r"(r[3]) : "r"(addr));
}

__device__ __forceinline__ void ldsm_x4_t(uint32_t* r, uint32_t addr) {
    asm volatile("ldmatrix.sync.aligned.m8n8.x4.trans.shared.b16 {%0,%1,%2,%3}, [%4];"
                 : "=r"(r[0]), "=r"(r[1]), "=r"(r[2]), "=r"(r[3]) : "r"(addr));
}

__device__ __forceinline__ void split2(float x, float y, uint32_t& hi, uint32_t& mid) {
    __nv_bfloat16 hx = __float2bfloat16(x);
    __nv_bfloat16 hy = __float2bfloat16(y);
    __nv_bfloat16 mx = __float2bfloat16(x - __bfloat162float(hx));
    __nv_bfloat16 my = __float2bfloat16(y - __bfloat162float(hy));
    hi  = ((uint32_t)__bfloat16_as_ushort(hy) << 16) | __bfloat16_as_ushort(hx);
    mid = ((uint32_t)__bfloat16_as_ushort(my) << 16) | __bfloat16_as_ushort(mx);
}

__device__ __forceinline__ void split1(float x, __nv_bfloat16& h, __nv_bfloat16& m) {
    h = __float2bfloat16(x);
    m = __float2bfloat16(x - __bfloat162float(h));
}

__device__ __forceinline__ void cp16(void* smem_ptr, const void* gmem_ptr) {
    uint32_t s = smem_u32(smem_ptr);
    asm volatile("cp.async.cg.shared.global [%0], [%1], 16;\n" :: "r"(s), "l"(gmem_ptr));
}
#define CP_COMMIT() asm volatile("cp.async.commit_group;\n" ::: "memory")
#define CP_WAIT0()  asm volatile("cp.async.wait_group 0;\n" ::: "memory")
#define CP_WAIT1()  asm volatile("cp.async.wait_group 1;\n" ::: "memory")
#define CP_WAIT2()  asm volatile("cp.async.wait_group 2;\n" ::: "memory")

// ---------------------------------------------------------------------------
// fp32 -> bf16 hi/mid split (elementwise)
// ---------------------------------------------------------------------------
__global__ void split_kernel(const float* __restrict__ src,
                             __nv_bfloat16* __restrict__ hi,
                             __nv_bfloat16* __restrict__ mid, int n4)
{
    int i = blockIdx.x * blockDim.x + threadIdx.x;
    if (i >= n4) return;
    float4 v = ((const float4*)src)[i];
    uint2 h, m;
    split2(v.x, v.y, h.x, m.x);
    split2(v.z, v.w, h.y, m.y);
    ((uint2*)hi)[i]  = h;
    ((uint2*)mid)[i] = m;
}

// ---------------------------------------------------------------------------
// Fused RoPE + split for Q (heads 0..31) and K (heads 32..39).
// ---------------------------------------------------------------------------
__global__ void rope_split_qk(const float* __restrict__ qkv,
                              const int* __restrict__ positions,
                              __nv_bfloat16* __restrict__ qh_, __nv_bfloat16* __restrict__ qm_,
                              __nv_bfloat16* __restrict__ kh_, __nv_bfloat16* __restrict__ km_)
{
    const int total = ROWS * (NQ + NKV) * (HD / 2);
    int idx = blockIdx.x * blockDim.x + threadIdx.x;
    if (idx >= total) return;

    const int i   = idx % (HD / 2);
    const int h   = (idx / (HD / 2)) % (NQ + NKV);
    const int row = idx / ((HD / 2) * (NQ + NKV));

    const int pos = positions[row & (SEQ - 1)];
    const float e = (float)(2 * i) / (float)HD;
    const float inv_freq = expf(-e * 9.210340371976184f);
    const float ang = (float)pos * inv_freq;
    float s, c;
    sincosf(ang, &s, &c);

    const float* base = qkv + (size_t)row * QKV_N + h * HD + i;
    const float t1 = base[0];
    const float t2 = base[HD / 2];
    const float o1 = t1 * c - t2 * s;
    const float o2 = t2 * c + t1 * s;

    __nv_bfloat16 h1, m1, h2, m2;
    split1(o1, h1, m1);
    split1(o2, h2, m2);

    if (h < NQ) {
        const size_t b = (size_t)row * EMBED + h * HD + i;
        qh_[b] = h1; qm_[b] = m1;
        qh_[b + HD/2] = h2; qm_[b + HD/2] = m2;
    } else {
        const int kvh = h - NQ;
        const int bb = row >> 11, ss = row & (SEQ - 1);
        const size_t b = ((size_t)(bb * NKV + kvh) * SEQ + ss) * HD + i;
        kh_[b] = h1; km_[b] = m1;
        kh_[b + HD/2] = h2; km_[b + HD/2] = m2;
    }
}

// ---------------------------------------------------------------------------
// V split (no rope, row-major [(bb*8+kvh)*2048+s][96]).
// ---------------------------------------------------------------------------
__global__ void split_v(const float* __restrict__ qkv,
                        __nv_bfloat16* __restrict__ vh_, __nv_bfloat16* __restrict__ vm_)
{
    const int total = ROWS * NKV * (HD / 4);
    int idx = blockIdx.x * blockDim.x + threadIdx.x;
    if (idx >= total) return;
    const int d4  = idx % (HD / 4);
    const int kvh = (idx / (HD / 4)) % NKV;
    const int row = idx / ((HD / 4) * NKV);
    const int bb = row >> 11, ss = row & (SEQ - 1);

    float4 v = *(const float4*)(qkv + (size_t)row * QKV_N + VOFF + kvh * HD + d4 * 4);
    uint2 h, m;
    split2(v.x, v.y, h.x, m.x);
    split2(v.z, v.w, h.y, m.y);
    const size_t b = ((size_t)(bb * NKV + kvh) * SEQ + ss) * HD + d4 * 4;
    *(uint2*)&vh_[b] = h;
    *(uint2*)&vm_[b] = m;
}

// ---------------------------------------------------------------------------
// Pre-split bf16 GEMM. BK=16, 4 cp.async stages, prefetch distance 3
// (wait_group 2; empty commits at the tail keep group accounting exact).
// CTA 128x128, 8 warps (4x2), ldmatrix fragments + B double buffer.
// ---------------------------------------------------------------------------
#define BM 128
#define BN 128
#define BK 16
#define SB 24                     // stride 24 bf16 = 12 banks -> conflict-free
#define ARR (128 * SB)            // one array per stage (bf16 elems)
#define STG (4 * ARR)             // Ahi,Ami,Bhi,Bmi
#define NSTAGE 4
#define GEMM_SMEM_BYTES (NSTAGE * STG * 2)   // 196,608... = 4*24576 = 98304 B

__global__ __launch_bounds__(256, 2) void gemm_pre(const __nv_bfloat16* __restrict__ Ah,
                                                   const __nv_bfloat16* __restrict__ Am,
                                                   const __nv_bfloat16* __restrict__ Bh,
                                                   const __nv_bfloat16* __restrict__ Bm,
                                                   float* __restrict__ C,
                                                   int M, int N, int K)
{
    extern __shared__ __nv_bfloat16 smem[];

    const int tid  = threadIdx.x;
    const int warp = tid >> 5;
    const int lane = tid & 31;
    const int m0 = blockIdx.y * BM;
    const int n0 = blockIdx.x * BN;

    const int wm = (warp >> 1) * 32;
    const int wn = (warp & 1) * 64;
    const int g  = lane >> 2;
    const int t4 = lane & 3;

    const int l7   = lane & 7;
    const int l8r  = lane & 8;
    const int l16h = (lane & 16) >> 1;

    // loader: row = tid>>1 (0..127), 16B chunk = (tid&1)*8 elems
    const int lrow = tid >> 1;
    const int lco  = (tid & 1) * 8;

    float acc[2][8][4];
#pragma unroll
    for (int mf = 0; mf < 2; mf++)
#pragma unroll
        for (int nf = 0; nf < 8; nf++)
#pragma unroll
            for (int r = 0; r < 4; r++) acc[mf][nf][r] = 0.0f;

    const size_t arow = (size_t)(m0 + lrow) * K;
    const size_t brow = (size_t)(n0 + lrow) * K;

    auto load_tile = [&](int k0, int stage) {
        __nv_bfloat16* s = smem + stage * STG;
        const int so = lrow * SB + lco;
        cp16(&s[so],         Ah + arow + k0 + lco);
        cp16(&s[ARR + so],   Am + arow + k0 + lco);
        cp16(&s[2*ARR + so], Bh + brow + k0 + lco);
        cp16(&s[3*ARR + so], Bm + brow + k0 + lco);
    };

    const int T = K / BK;   // 192
    load_tile(0, 0);        CP_COMMIT();
    load_tile(BK, 1);       CP_COMMIT();
    load_tile(2 * BK, 2);   CP_COMMIT();

    for (int t = 0; t < T; t++) {
        CP_WAIT2();          // tile t resident (3 groups max outstanding)
        __syncthreads();
        if (t + 3 < T) load_tile((t + 3) * BK, (t + 3) & 3);
        CP_COMMIT();         // possibly-empty group keeps the count exact

        const __nv_bfloat16* base = smem + (t & 3) * STG;
        const uint32_t aAh = smem_u32(base) + ((wm + l7 + l8r) * SB + l16h) * 2;
        const uint32_t aAm = aAh + ARR * 2;
        const uint32_t aBh = smem_u32(base) + (2 * ARR + (wn + l7 + l16h) * SB + l8r) * 2;
        const uint32_t aBm = aBh + ARR * 2;

        uint32_t ahi[2][4], ami[2][4];
        ldsm_x4(ahi[0], aAh);
        ldsm_x4(ahi[1], aAh + (16 * SB * 2));
        ldsm_x4(ami[0], aAm);
        ldsm_x4(ami[1], aAm + (16 * SB * 2));

        uint32_t bh[2][4], bm[2][4];
        ldsm_x4(bh[0], aBh);
        ldsm_x4(bm[0], aBm);

#pragma unroll
        for (int nfp = 0; nfp < 4; nfp++) {
            const int cur = nfp & 1, nxt = cur ^ 1;
            if (nfp < 3) {
                ldsm_x4(bh[nxt], aBh + (nfp + 1) * (16 * SB * 2));
                ldsm_x4(bm[nxt], aBm + (nfp + 1) * (16 * SB * 2));
            }
            const int n0f = nfp * 2, n1f = n0f + 1;
            mma_bf16(acc[0][n0f], ahi[0], bh[cur]);
            mma_bf16(acc[1][n0f], ahi[1], bh[cur]);
            mma_bf16(acc[0][n1f], ahi[0], bh[cur] + 2);
            mma_bf16(acc[1][n1f], ahi[1], bh[cur] + 2);
            mma_bf16(acc[0][n0f], ami[0], bh[cur]);
            mma_bf16(acc[1][n0f], ami[1], bh[cur]);
            mma_bf16(acc[0][n1f], ami[0], bh[cur] + 2);
            mma_bf16(acc[1][n1f], ami[1], bh[cur] + 2);
            mma_bf16(acc[0][n0f], ahi[0], bm[cur]);
            mma_bf16(acc[1][n0f], ahi[1], bm[cur]);
            mma_bf16(acc[0][n1f], ahi[0], bm[cur] + 2);
            mma_bf16(acc[1][n1f], ahi[1], bm[cur] + 2);
        }
        // no trailing barrier: WAR on stage (t+3)&3 ordered by next iters' sync
    }

#pragma unroll
    for (int mf = 0; mf < 2; mf++) {
#pragma unroll
        for (int nf = 0; nf < 8; nf++) {
            const int r = m0 + wm + mf * 16 + g;
            const int c = n0 + wn + nf * 8 + 2 * t4;
            float2 v0 = {acc[mf][nf][0], acc[mf][nf][1]};
            float2 v1 = {acc[mf][nf][2], acc[mf][nf][3]};
            *(float2*)(C + (size_t)r * N + c)       = v0;
            *(float2*)(C + (size_t)(r + 8) * N + c) = v1;
        }
    }
}

// ---------------------------------------------------------------------------
// Causal GQA flash attention (unchanged from R12/R13).
// ---------------------------------------------------------------------------
#define AQS 104
#define APS 72
#define ATTN_SM_BYTES ((6*64*AQS + 2*64*APS) * 2 + 2 * 128 * 4)   // 99,328 B

__global__ __launch_bounds__(256, 2) void attn_mma(
    const __nv_bfloat16* __restrict__ qh_, const __nv_bfloat16* __restrict__ qm_,
    const __nv_bfloat16* __restrict__ kh_, const __nv_bfloat16* __restrict__ km_,
    const __nv_bfloat16* __restrict__ vh_, const __nv_bfloat16* __restrict__ vm_,
    __nv_bfloat16* __restrict__ outH, __nv_bfloat16* __restrict__ outM)
{
    extern __shared__ char sm_raw[];
    __nv_bfloat16* Qhi = (__nv_bfloat16*)sm_raw;
    __nv_bfloat16* Qmi = Qhi + 64 * AQS;
    __nv_bfloat16* Khi = Qmi + 64 * AQS;
    __nv_bfloat16* Kmi = Khi + 64 * AQS;
    __nv_bfloat16* Vhi = Kmi + 64 * AQS;
    __nv_bfloat16* Vmi = Vhi + 64 * AQS;
    __nv_bfloat16* Phi = Vmi + 64 * AQS;
    __nv_bfloat16* Pmi = Phi + 64 * APS;
    float* redM = (float*)(Pmi + 64 * APS);
    float* redL = redM + 128;

    const int qb = blockIdx.x;
    const int qh = blockIdx.y;
    const int bb = blockIdx.z;
    const int kvh = qh >> 2;
    const int tid = threadIdx.x, warp = tid >> 5, lane = tid & 31;
    const int wy = warp >> 1, wx = warp & 1;
    const int g = lane >> 2, t4 = lane & 3;
    const int r0 = wy * 16 + g, r1 = r0 + 8;
    const float scale = 0.10206207261596577f;

    const int l7   = lane & 7;
    const int l8r  = lane & 8;
    const int l16h = (lane & 16) >> 1;

    const uint32_t aQh = smem_u32(Qhi) + ((wy * 16 + l7 + l8r) * AQS + l16h) * 2;
    const uint32_t aQm = aQh + (64 * AQS) * 2;
    const uint32_t aKh = smem_u32(Khi) + ((wx * 32 + l7 + l16h) * AQS + l8r) * 2;
    const uint32_t aKm = aKh + (64 * AQS) * 2;
    const uint32_t aVh = smem_u32(Vhi) + ((l7 + l8r) * AQS + wx * 48 + l16h) * 2;
    const uint32_t aVm = aVh + (64 * AQS) * 2;
    const uint32_t aPh = smem_u32(Phi) + ((wy * 16 + l7 + l8r) * APS + l16h) * 2;
    const uint32_t aPm = aPh + (64 * APS) * 2;

    const __nv_bfloat16* qsrcH = qh_ + (size_t)(bb * SEQ + qb * 64) * EMBED + qh * HD;
    const __nv_bfloat16* qsrcM = qm_ + (size_t)(bb * SEQ + qb * 64) * EMBED + qh * HD;
    const size_t kvbase = (size_t)(bb * NKV + kvh) * SEQ * HD;

    auto load_q = [&]() {
#pragma unroll
        for (int j = 0; j < 3; j++) {
            const int idx = tid + j * 256;
            const int r = idx / 12, c = idx % 12;
            cp16(&Qhi[r * AQS + c * 8], qsrcH + (size_t)r * EMBED + c * 8);
            cp16(&Qmi[r * AQS + c * 8], qsrcM + (size_t)r * EMBED + c * 8);
        }
    };
    auto load_k = [&](int kb) {
        const __nv_bfloat16* sh = kh_ + kvbase + (size_t)kb * 64 * HD;
        const __nv_bfloat16* sm2 = km_ + kvbase + (size_t)kb * 64 * HD;
#pragma unroll
        for (int j = 0; j < 3; j++) {
            const int idx = tid + j * 256;
            const int r = idx / 12, c = idx % 12;
            cp16(&Khi[r * AQS + c * 8], sh + r * HD + c * 8);
            cp16(&Kmi[r * AQS + c * 8], sm2 + r * HD + c * 8);
        }
    };
    auto load_v = [&](int kb) {
        const __nv_bfloat16* sh = vh_ + kvbase + (size_t)kb * 64 * HD;
        const __nv_bfloat16* sm2 = vm_ + kvbase + (size_t)kb * 64 * HD;
#pragma unroll
        for (int j = 0; j < 3; j++) {
            const int idx = tid + j * 256;
            const int r = idx / 12, c = idx % 12;
            cp16(&Vhi[r * AQS + c * 8], sh + r * HD + c * 8);
            cp16(&Vmi[r * AQS + c * 8], sm2 + r * HD + c * 8);
        }
    };

    load_q();
    load_k(0);
    CP_COMMIT();
    load_v(0);
    CP_COMMIT();

    float accO[6][4];
#pragma unroll
    for (int nf = 0; nf < 6; nf++)
#pragma unroll
        for (int e = 0; e < 4; e++) accO[nf][e] = 0.0f;
    float m_run0 = -1e30f, m_run1 = -1e30f, l_run0 = 0.0f, l_run1 = 0.0f;

    for (int kb = 0; kb <= qb; kb++) {
        CP_WAIT1();
        __syncthreads();

        float s[4][4];
#pragma unroll
        for (int nf = 0; nf < 4; nf++)
#pragma unroll
            for (int e = 0; e < 4; e++) s[nf][e] = 0.0f;

#pragma unroll
        for (int ks = 0; ks < 6; ks++) {
            const uint32_t ko = ks * 32;
            uint32_t ah[4], am[4];
            ldsm_x4(ah, aQh + ko);
            ldsm_x4(am, aQm + ko);
#pragma unroll
            for (int nfp = 0; nfp < 2; nfp++) {
                uint32_t bh[4], bm[4];
                ldsm_x4(bh, aKh + nfp * (16 * AQS * 2) + ko);
                ldsm_x4(bm, aKm + nfp * (16 * AQS * 2) + ko);
                const int n0f = nfp * 2, n1f = n0f + 1;
                mma_bf16(s[n0f], ah, bh);
                mma_bf16(s[n1f], ah, bh + 2);
                mma_bf16(s[n0f], am, bh);
                mma_bf16(s[n1f], am, bh + 2);
                mma_bf16(s[n0f], ah, bm);
                mma_bf16(s[n1f], ah, bm + 2);
            }
        }

        const int rowg0 = qb * 64 + r0, rowg1 = qb * 64 + r1;
#pragma unroll
        for (int nf = 0; nf < 4; nf++) {
            const int cg = kb * 64 + wx * 32 + nf * 8 + 2 * t4;
            s[nf][0] = (cg     > rowg0) ? -1e30f : s[nf][0] * scale;
            s[nf][1] = (cg + 1 > rowg0) ? -1e30f : s[nf][1] * scale;
            s[nf][2] = (cg     > rowg1) ? -1e30f : s[nf][2] * scale;
            s[nf][3] = (cg + 1 > rowg1) ? -1e30f : s[nf][3] * scale;
        }

        float mr0 = s[0][0], mr1 = s[0][2];
#pragma unroll
        for (int nf = 0; nf < 4; nf++) {
            mr0 = fmaxf(mr0, fmaxf(s[nf][0], s[nf][1]));
            mr1 = fmaxf(mr1, fmaxf(s[nf][2], s[nf][3]));
        }
        mr0 = fmaxf(mr0, __shfl_xor_sync(0xffffffffu, mr0, 1));
        mr0 = fmaxf(mr0, __shfl_xor_sync(0xffffffffu, mr0, 2));
        mr1 = fmaxf(mr1, __shfl_xor_sync(0xffffffffu, mr1, 1));
        mr1 = fmaxf(mr1, __shfl_xor_sync(0xffffffffu, mr1, 2));
        if (t4 == 0) {
            redM[wx * 64 + r0] = mr0;
            redM[wx * 64 + r1] = mr1;
        }
        __syncthreads();
        if (kb < qb) { load_k(kb + 1); CP_COMMIT(); }

        mr0 = fmaxf(mr0, redM[(1 - wx) * 64 + r0]);
        mr1 = fmaxf(mr1, redM[(1 - wx) * 64 + r1]);

        const float mn0 = fmaxf(m_run0, mr0), mn1 = fmaxf(m_run1, mr1);
        const float co0 = __expf(m_run0 - mn0), co1 = __expf(m_run1 - mn1);
        m_run0 = mn0; m_run1 = mn1;

        float sum0 = 0.0f, sum1 = 0.0f;
#pragma unroll
        for (int nf = 0; nf < 4; nf++) {
            s[nf][0] = __expf(s[nf][0] - mn0);
            s[nf][1] = __expf(s[nf][1] - mn0);
            s[nf][2] = __expf(s[nf][2] - mn1);
            s[nf][3] = __expf(s[nf][3] - mn1);
            sum0 += s[nf][0] + s[nf][1];
            sum1 += s[nf][2] + s[nf][3];
            const int c = wx * 32 + nf * 8 + 2 * t4;
            uint32_t hw, mw;
            split2(s[nf][0], s[nf][1], hw, mw);
            *(uint32_t*)&Phi[r0 * APS + c] = hw;
            *(uint32_t*)&Pmi[r0 * APS + c] = mw;
            split2(s[nf][2], s[nf][3], hw, mw);
            *(uint32_t*)&Phi[r1 * APS + c] = hw;
            *(uint32_t*)&Pmi[r1 * APS + c] = mw;
        }
        sum0 += __shfl_xor_sync(0xffffffffu, sum0, 1);
        sum0 += __shfl_xor_sync(0xffffffffu, sum0, 2);
        sum1 += __shfl_xor_sync(0xffffffffu, sum1, 1);
        sum1 += __shfl_xor_sync(0xffffffffu, sum1, 2);
        if (t4 == 0) {
            redL[wx * 64 + r0] = sum0;
            redL[wx * 64 + r1] = sum1;
        }
        if (kb < qb) CP_WAIT1(); else CP_WAIT0();
        __syncthreads();
        l_run0 = l_run0 * co0 + redL[r0] + redL[64 + r0];
        l_run1 = l_run1 * co1 + redL[r1] + redL[64 + r1];

#pragma unroll
        for (int nf = 0; nf < 6; nf++) {
            accO[nf][0] *= co0; accO[nf][1] *= co0;
            accO[nf][2] *= co1; accO[nf][3] *= co1;
        }
#pragma unroll
        for (int ks = 0; ks < 4; ks++) {
            const uint32_t kop = ks * 32;
            const uint32_t kov = ks * (16 * AQS * 2);
            uint32_t ah[4], am[4];
            ldsm_x4(ah, aPh + kop);
            ldsm_x4(am, aPm + kop);
#pragma unroll
            for (int nfp = 0; nfp < 3; nfp++) {
                uint32_t bh[4], bm[4];
                ldsm_x4_t(bh, aVh + kov + nfp * 32);
                ldsm_x4_t(bm, aVm + kov + nfp * 32);
                const int n0f = nfp * 2, n1f = n0f + 1;
                mma_bf16(accO[n0f], ah, bh);
                mma_bf16(accO[n1f], ah, bh + 2);
                mma_bf16(accO[n0f], am, bh);
                mma_bf16(accO[n1f], am, bh + 2);
                mma_bf16(accO[n0f], ah, bm);
                mma_bf16(accO[n1f], ah, bm + 2);
            }
        }
        __syncthreads();
        if (kb < qb) { load_v(kb + 1); CP_COMMIT(); }
    }

    const float il0 = 1.0f / l_run0, il1 = 1.0f / l_run1;
    const size_t row0 = (size_t)(bb * SEQ + qb * 64 + r0);
    const size_t row1 = (size_t)(bb * SEQ + qb * 64 + r1);
#pragma unroll
    for (int nf = 0; nf < 6; nf++) {
        const int c = qh * HD + wx * 48 + nf * 8 + 2 * t4;
        uint32_t h, m;
        split2(accO[nf][0] * il0, accO[nf][1] * il0, h, m);
        *(uint32_t*)&outH[row0 * EMBED + c] = h;
        *(uint32_t*)&outM[row0 * EMBED + c] = m;
        split2(accO[nf][2] * il1, accO[nf][3] * il1, h, m);
        *(uint32_t*)&outH[row1 * EMBED + c] = h;
        *(uint32_t*)&outM[row1 * EMBED + c] = m;
    }
}

// ---------------------------------------------------------------------------
// Launch
// ---------------------------------------------------------------------------
extern "C" void kernel_launch(void* const* d_in, const int* in_sizes, int n_in,
                              void* d_out, int out_size)
{
    const float* x         = (const float*)d_in[0];
    const int*   positions = (const int*)d_in[1];
    const float* W_qkv     = (const float*)d_in[3];
    const float* W_o       = (const float*)d_in[4];
    float* out = (float*)d_out;

    float* qkv;  cudaGetSymbolAddress((void**)&qkv,  g_qkv);
    __nv_bfloat16 *xh, *xm, *wqh, *wqm, *woh, *wom, *ah, *am;
    __nv_bfloat16 *qsh, *qsm, *ksh, *ksm, *vsh, *vsm;
    cudaGetSymbolAddress((void**)&xh,  g_xh);   cudaGetSymbolAddress((void**)&xm,  g_xm);
    cudaGetSymbolAddress((void**)&wqh, g_wqh);  cudaGetSymbolAddress((void**)&wqm, g_wqm);
    cudaGetSymbolAddress((void**)&woh, g_woh);  cudaGetSymbolAddress((void**)&wom, g_wom);
    cudaGetSymbolAddress((void**)&ah,  g_ah);   cudaGetSymbolAddress((void**)&am,  g_am);
    cudaGetSymbolAddress((void**)&qsh, g_qsh);  cudaGetSymbolAddress((void**)&qsm, g_qsm);
    cudaGetSymbolAddress((void**)&ksh, g_ksh);  cudaGetSymbolAddress((void**)&ksm, g_ksm);
    cudaGetSymbolAddress((void**)&vsh, g_vsh);  cudaGetSymbolAddress((void**)&vsm, g_vsm);

    cudaFuncSetAttribute(attn_mma, cudaFuncAttributeMaxDynamicSharedMemorySize,
                         ATTN_SM_BYTES);
    cudaFuncSetAttribute(gemm_pre, cudaFuncAttributeMaxDynamicSharedMemorySize,
                         GEMM_SMEM_BYTES);

    // 0) pre-split inputs/weights
    {
        int n4;
        n4 = ROWS * EMBED / 4;
        split_kernel<<<(n4 + 255) / 256, 256>>>(x, xh, xm, n4);
        n4 = QKV_N * EMBED / 4;
        split_kernel<<<(n4 + 255) / 256, 256>>>(W_qkv, wqh, wqm, n4);
        n4 = EMBED * EMBED / 4;
        split_kernel<<<(n4 + 255) / 256, 256>>>(W_o, woh, wom, n4);
    }

    // 1) QKV projection
    gemm_pre<<<dim3(QKV_N / 128, ROWS / 128), 256, GEMM_SMEM_BYTES>>>(
        xh, xm, wqh, wqm, qkv, ROWS, QKV_N, EMBED);

    // 2) RoPE + pre-split Q,K ; pre-split V
    {
        const int totqk = ROWS * (NQ + NKV) * (HD / 2);
        rope_split_qk<<<(totqk + 255) / 256, 256>>>(qkv, positions, qsh, qsm, ksh, ksm);
        const int totv = ROWS * NKV * (HD / 4);
        split_v<<<(totv + 255) / 256, 256>>>(qkv, vsh, vsm);
    }

    // 3) Causal GQA attention -> pre-split O
    attn_mma<<<dim3(SEQ / 64, NQ, BATCH), 256, ATTN_SM_BYTES>>>(
        qsh, qsm, ksh, ksm, vsh, vsm, ah, am);

    // 4) Output projection
    gemm_pre<<<dim3(EMBED / 128, ROWS / 128), 256, GEMM_SMEM_BYTES>>>(
        ah, am, woh, wom, out, ROWS, EMBED, EMBED);
}

// round 16
// speedup vs baseline: 2.0448x; 1.4971x over previous
#include <cuda_runtime.h>
#include <cuda_fp16.h>
#include <math.h>
#include <stdint.h>

#define EMBED 3072
#define NQ 32
#define NKV 8
#define HD 96
#define BATCH 2
#define SEQ 2048
#define ROWS (BATCH*SEQ)                 // 4096
#define QKV_N (NQ*HD + 2*NKV*HD)         // 4608
#define KOFF (NQ*HD)                     // 3072
#define VOFF (NQ*HD + NKV*HD)            // 3840

// Scratch (allocation-free rule: __device__ globals)
__device__ float g_qkv[ROWS * QKV_N];
__device__ __half g_xh[ROWS * EMBED],  g_xm[ROWS * EMBED];   // x hi/lo
__device__ __half g_wqh[QKV_N * EMBED];                      // W_qkv (rounded)
__device__ __half g_woh[EMBED * EMBED];                      // W_o (rounded)
__device__ __half g_ah[ROWS * EMBED],  g_am[ROWS * EMBED];   // attn out hi/lo
__device__ __half g_qsh[ROWS * EMBED], g_qsm[ROWS * EMBED];  // Q post-rope hi/lo
__device__ __half g_ksh[BATCH*NKV*SEQ*HD];                   // K post-rope (rounded)
__device__ __half g_vsh[BATCH*NKV*SEQ*HD];                   // V (rounded)

// ---------------------------------------------------------------------------
// Helpers
// ---------------------------------------------------------------------------
__device__ __forceinline__ uint32_t smem_u32(const void* p) {
    return (uint32_t)__cvta_generic_to_shared(p);
}

__device__ __forceinline__ void mma_f16(float* d, const uint32_t* a, const uint32_t* b) {
    asm volatile(
        "mma.sync.aligned.m16n8k16.row.col.f32.f16.f16.f32 "
        "{%0,%1,%2,%3}, {%4,%5,%6,%7}, {%8,%9}, {%0,%1,%2,%3};"
        : "+f"(d[0]), "+f"(d[1]), "+f"(d[2]), "+f"(d[3])
        : "r"(a[0]), "r"(a[1]), "r"(a[2]), "r"(a[3]), "r"(b[0]), "r"(b[1]));
}

__device__ __forceinline__ void ldsm_x4(uint32_t* r, uint32_t addr) {
    asm volatile("ldmatrix.sync.aligned.m8n8.x4.shared.b16 {%0,%1,%2,%3}, [%4];"
                 : "=r"(r[0]), "=r"(r[1]), "=r"(r[2]), "=r"(r[3]) : "r"(addr));
}

__device__ __forceinline__ void ldsm_x4_t(uint32_t* r, uint32_t addr) {
    asm volatile("ldmatrix.sync.aligned.m8n8.x4.trans.shared.b16 {%0,%1,%2,%3}, [%4];"
                 : "=r"(r[0]), "=r"(r[1]), "=r"(r[2]), "=r"(r[3]) : "r"(addr));
}

// two floats -> fp16 hi word + fp16 lo (residual) word
__device__ __forceinline__ void split2h(float x, float y, uint32_t& hi, uint32_t& lo) {
    __half hx = __float2half(x);
    __half hy = __float2half(y);
    __half lx = __float2half(x - __half2float(hx));
    __half ly = __float2half(y - __half2float(hy));
    hi = ((uint32_t)__half_as_ushort(hy) << 16) | __half_as_ushort(hx);
    lo = ((uint32_t)__half_as_ushort(ly) << 16) | __half_as_ushort(lx);
}

__device__ __forceinline__ uint32_t round2h(float x, float y) {
    return ((uint32_t)__half_as_ushort(__float2half(y)) << 16)
         | __half_as_ushort(__float2half(x));
}

__device__ __forceinline__ void cp16(void* smem_ptr, const void* gmem_ptr) {
    uint32_t s = smem_u32(smem_ptr);
    asm volatile("cp.async.cg.shared.global [%0], [%1], 16;\n" :: "r"(s), "l"(gmem_ptr));
}
#define CP_COMMIT() asm volatile("cp.async.commit_group;\n" ::: "memory")
#define CP_WAIT0()  asm volatile("cp.async.wait_group 0;\n" ::: "memory")
#define CP_WAIT1()  asm volatile("cp.async.wait_group 1;\n" ::: "memory")
#define CP_WAIT2()  asm volatile("cp.async.wait_group 2;\n" ::: "memory")

// ---------------------------------------------------------------------------
// fp32 -> fp16 hi/lo split (elementwise)
// ---------------------------------------------------------------------------
__global__ void split_kernel(const float* __restrict__ src,
                             __half* __restrict__ hi,
                             __half* __restrict__ lo, int n4)
{
    int i = blockIdx.x * blockDim.x + threadIdx.x;
    if (i >= n4) return;
    float4 v = ((const float4*)src)[i];
    uint2 h, m;
    split2h(v.x, v.y, h.x, m.x);
    split2h(v.z, v.w, h.y, m.y);
    ((uint2*)hi)[i] = h;
    ((uint2*)lo)[i] = m;
}

// fp32 -> fp16 rounding only (weights / single-precision side)
__global__ void round_kernel(const float* __restrict__ src,
                             __half* __restrict__ dst, int n4)
{
    int i = blockIdx.x * blockDim.x + threadIdx.x;
    if (i >= n4) return;
    float4 v = ((const float4*)src)[i];
    uint2 r = {round2h(v.x, v.y), round2h(v.z, v.w)};
    ((uint2*)dst)[i] = r;
}

// ---------------------------------------------------------------------------
// Fused RoPE + convert: Q (heads 0..31) -> fp16 hi/lo, K (32..39) -> fp16.
// ---------------------------------------------------------------------------
__global__ void rope_split_qk(const float* __restrict__ qkv,
                              const int* __restrict__ positions,
                              __half* __restrict__ qh_, __half* __restrict__ qm_,
                              __half* __restrict__ kh_)
{
    const int total = ROWS * (NQ + NKV) * (HD / 2);
    int idx = blockIdx.x * blockDim.x + threadIdx.x;
    if (idx >= total) return;

    const int i   = idx % (HD / 2);
    const int h   = (idx / (HD / 2)) % (NQ + NKV);
    const int row = idx / ((HD / 2) * (NQ + NKV));

    const int pos = positions[row & (SEQ - 1)];
    const float e = (float)(2 * i) / (float)HD;
    const float inv_freq = expf(-e * 9.210340371976184f);
    const float ang = (float)pos * inv_freq;
    float s, c;
    sincosf(ang, &s, &c);

    const float* base = qkv + (size_t)row * QKV_N + h * HD + i;
    const float t1 = base[0];
    const float t2 = base[HD / 2];
    const float o1 = t1 * c - t2 * s;
    const float o2 = t2 * c + t1 * s;

    if (h < NQ) {
        const size_t b = (size_t)row * EMBED + h * HD + i;
        __half h1 = __float2half(o1), h2 = __float2half(o2);
        qh_[b] = h1;
        qh_[b + HD/2] = h2;
        qm_[b] = __float2half(o1 - __half2float(h1));
        qm_[b + HD/2] = __float2half(o2 - __half2float(h2));
    } else {
        const int kvh = h - NQ;
        const int bb = row >> 11, ss = row & (SEQ - 1);
        const size_t b = ((size_t)(bb * NKV + kvh) * SEQ + ss) * HD + i;
        kh_[b] = __float2half(o1);
        kh_[b + HD/2] = __float2half(o2);
    }
}

// ---------------------------------------------------------------------------
// V: round to fp16, row-major [(bb*8+kvh)*2048+s][96].
// ---------------------------------------------------------------------------
__global__ void round_v(const float* __restrict__ qkv,
                        __half* __restrict__ vh_)
{
    const int total = ROWS * NKV * (HD / 4);
    int idx = blockIdx.x * blockDim.x + threadIdx.x;
    if (idx >= total) return;
    const int d4  = idx % (HD / 4);
    const int kvh = (idx / (HD / 4)) % NKV;
    const int row = idx / ((HD / 4) * NKV);
    const int bb = row >> 11, ss = row & (SEQ - 1);

    float4 v = *(const float4*)(qkv + (size_t)row * QKV_N + VOFF + kvh * HD + d4 * 4);
    const size_t b = ((size_t)(bb * NKV + kvh) * SEQ + ss) * HD + d4 * 4;
    uint2 r = {round2h(v.x, v.y), round2h(v.z, v.w)};
    *(uint2*)&vh_[b] = r;
}

// ---------------------------------------------------------------------------
// fp16 2-term GEMM: C = (Ahi+Alo) * Bh^T.  BK=16, 4 cp.async stages,
// prefetch distance 3. CTA 128x128, 8 warps (4x2), ldmatrix fragments.
// ---------------------------------------------------------------------------
#define BM 128
#define BN 128
#define BK 16
#define SB 24                     // stride 24 fp16 = 12 banks -> conflict-free
#define ARR (128 * SB)
#define STG (3 * ARR)             // Ahi, Alo, Bh
#define NSTAGE 4
#define GEMM_SMEM_BYTES (NSTAGE * STG * 2)   // 73,728 B

__global__ __launch_bounds__(256, 2) void gemm_pre(const __half* __restrict__ Ah,
                                                   const __half* __restrict__ Al,
                                                   const __half* __restrict__ Bh,
                                                   float* __restrict__ C,
                                                   int M, int N, int K)
{
    extern __shared__ __half smem[];

    const int tid  = threadIdx.x;
    const int warp = tid >> 5;
    const int lane = tid & 31;
    const int m0 = blockIdx.y * BM;
    const int n0 = blockIdx.x * BN;

    const int wm = (warp >> 1) * 32;
    const int wn = (warp & 1) * 64;
    const int g  = lane >> 2;
    const int t4 = lane & 3;

    const int l7   = lane & 7;
    const int l8r  = lane & 8;
    const int l16h = (lane & 16) >> 1;

    const int lrow = tid >> 1;
    const int lco  = (tid & 1) * 8;

    float acc[2][8][4];
#pragma unroll
    for (int mf = 0; mf < 2; mf++)
#pragma unroll
        for (int nf = 0; nf < 8; nf++)
#pragma unroll
            for (int r = 0; r < 4; r++) acc[mf][nf][r] = 0.0f;

    const size_t arow = (size_t)(m0 + lrow) * K;
    const size_t brow = (size_t)(n0 + lrow) * K;

    auto load_tile = [&](int k0, int stage) {
        __half* s = smem + stage * STG;
        const int so = lrow * SB + lco;
        cp16(&s[so],         Ah + arow + k0 + lco);
        cp16(&s[ARR + so],   Al + arow + k0 + lco);
        cp16(&s[2*ARR + so], Bh + brow + k0 + lco);
    };

    const int T = K / BK;   // 192
    load_tile(0, 0);        CP_COMMIT();
    load_tile(BK, 1);       CP_COMMIT();
    load_tile(2 * BK, 2);   CP_COMMIT();

    for (int t = 0; t < T; t++) {
        CP_WAIT2();
        __syncthreads();
        if (t + 3 < T) load_tile((t + 3) * BK, (t + 3) & 3);
        CP_COMMIT();     // possibly-empty group keeps the accounting exact

        const __half* base = smem + (t & 3) * STG;
        const uint32_t aAh = smem_u32(base) + ((wm + l7 + l8r) * SB + l16h) * 2;
        const uint32_t aAl = aAh + ARR * 2;
        const uint32_t aBh = smem_u32(base) + (2 * ARR + (wn + l7 + l16h) * SB + l8r) * 2;

        uint32_t ahi[2][4], alo[2][4];
        ldsm_x4(ahi[0], aAh);
        ldsm_x4(ahi[1], aAh + (16 * SB * 2));
        ldsm_x4(alo[0], aAl);
        ldsm_x4(alo[1], aAl + (16 * SB * 2));

        uint32_t bh[2][4];
        ldsm_x4(bh[0], aBh);

#pragma unroll
        for (int nfp = 0; nfp < 4; nfp++) {
            const int cur = nfp & 1, nxt = cur ^ 1;
            if (nfp < 3) ldsm_x4(bh[nxt], aBh + (nfp + 1) * (16 * SB * 2));
            const int n0f = nfp * 2, n1f = n0f + 1;
            mma_f16(acc[0][n0f], ahi[0], bh[cur]);
            mma_f16(acc[1][n0f], ahi[1], bh[cur]);
            mma_f16(acc[0][n1f], ahi[0], bh[cur] + 2);
            mma_f16(acc[1][n1f], ahi[1], bh[cur] + 2);
            mma_f16(acc[0][n0f], alo[0], bh[cur]);
            mma_f16(acc[1][n0f], alo[1], bh[cur]);
            mma_f16(acc[0][n1f], alo[0], bh[cur] + 2);
            mma_f16(acc[1][n1f], alo[1], bh[cur] + 2);
        }
    }

#pragma unroll
    for (int mf = 0; mf < 2; mf++) {
#pragma unroll
        for (int nf = 0; nf < 8; nf++) {
            const int r = m0 + wm + mf * 16 + g;
            const int c = n0 + wn + nf * 8 + 2 * t4;
            float2 v0 = {acc[mf][nf][0], acc[mf][nf][1]};
            float2 v1 = {acc[mf][nf][2], acc[mf][nf][3]};
            *(float2*)(C + (size_t)r * N + c)       = v0;
            *(float2*)(C + (size_t)(r + 8) * N + c) = v1;
        }
    }
}

// ---------------------------------------------------------------------------
// Causal GQA flash attention: Q 2-term fp16, K/V single fp16.
// Strides: Q/K/V 104 fp16 rows, P 72.
// ---------------------------------------------------------------------------
#define AQS 104
#define APS 72
#define ATTN_SM_BYTES ((4*64*AQS + 2*64*APS) * 2 + 2 * 128 * 4)   // 72,704 B

__global__ __launch_bounds__(256, 2) void attn_mma(
    const __half* __restrict__ qh_, const __half* __restrict__ qm_,
    const __half* __restrict__ kh_, const __half* __restrict__ vh_,
    __half* __restrict__ outH, __half* __restrict__ outM)
{
    extern __shared__ char sm_raw[];
    __half* Qhi = (__half*)sm_raw;
    __half* Qlo = Qhi + 64 * AQS;
    __half* Khi = Qlo + 64 * AQS;
    __half* Vhi = Khi + 64 * AQS;
    __half* Phi = Vhi + 64 * AQS;
    __half* Plo = Phi + 64 * APS;
    float* redM = (float*)(Plo + 64 * APS);
    float* redL = redM + 128;

    const int qb = blockIdx.x;
    const int qh = blockIdx.y;
    const int bb = blockIdx.z;
    const int kvh = qh >> 2;
    const int tid = threadIdx.x, warp = tid >> 5, lane = tid & 31;
    const int wy = warp >> 1, wx = warp & 1;
    const int g = lane >> 2, t4 = lane & 3;
    const int r0 = wy * 16 + g, r1 = r0 + 8;
    const float scale = 0.10206207261596577f;

    const int l7   = lane & 7;
    const int l8r  = lane & 8;
    const int l16h = (lane & 16) >> 1;

    const uint32_t aQh = smem_u32(Qhi) + ((wy * 16 + l7 + l8r) * AQS + l16h) * 2;
    const uint32_t aQl = aQh + (64 * AQS) * 2;
    const uint32_t aKh = smem_u32(Khi) + ((wx * 32 + l7 + l16h) * AQS + l8r) * 2;
    const uint32_t aVh = smem_u32(Vhi) + ((l7 + l8r) * AQS + wx * 48 + l16h) * 2;
    const uint32_t aPh = smem_u32(Phi) + ((wy * 16 + l7 + l8r) * APS + l16h) * 2;
    const uint32_t aPl = aPh + (64 * APS) * 2;

    const __half* qsrcH = qh_ + (size_t)(bb * SEQ + qb * 64) * EMBED + qh * HD;
    const __half* qsrcM = qm_ + (size_t)(bb * SEQ + qb * 64) * EMBED + qh * HD;
    const size_t kvbase = (size_t)(bb * NKV + kvh) * SEQ * HD;

    auto load_q = [&]() {
#pragma unroll
        for (int j = 0; j < 3; j++) {
            const int idx = tid + j * 256;
            const int r = idx / 12, c = idx % 12;
            cp16(&Qhi[r * AQS + c * 8], qsrcH + (size_t)r * EMBED + c * 8);
            cp16(&Qlo[r * AQS + c * 8], qsrcM + (size_t)r * EMBED + c * 8);
        }
    };
    auto load_k = [&](int kb) {
        const __half* sh = kh_ + kvbase + (size_t)kb * 64 * HD;
#pragma unroll
        for (int j = 0; j < 3; j++) {
            const int idx = tid + j * 256;
            const int r = idx / 12, c = idx % 12;
            cp16(&Khi[r * AQS + c * 8], sh + r * HD + c * 8);
        }
    };
    auto load_v = [&](int kb) {
        const __half* sh = vh_ + kvbase + (size_t)kb * 64 * HD;
#pragma unroll
        for (int j = 0; j < 3; j++) {
            const int idx = tid + j * 256;
            const int r = idx / 12, c = idx % 12;
            cp16(&Vhi[r * AQS + c * 8], sh + r * HD + c * 8);
        }
    };

    load_q();
    load_k(0);
    CP_COMMIT();
    load_v(0);
    CP_COMMIT();

    float accO[6][4];
#pragma unroll
    for (int nf = 0; nf < 6; nf++)
#pragma unroll
        for (int e = 0; e < 4; e++) accO[nf][e] = 0.0f;
    float m_run0 = -1e30f, m_run1 = -1e30f, l_run0 = 0.0f, l_run1 = 0.0f;

    for (int kb = 0; kb <= qb; kb++) {
        CP_WAIT1();
        __syncthreads();

        float s[4][4];
#pragma unroll
        for (int nf = 0; nf < 4; nf++)
#pragma unroll
            for (int e = 0; e < 4; e++) s[nf][e] = 0.0f;

#pragma unroll
        for (int ks = 0; ks < 6; ks++) {
            const uint32_t ko = ks * 32;
            uint32_t ah[4], al[4];
            ldsm_x4(ah, aQh + ko);
            ldsm_x4(al, aQl + ko);
#pragma unroll
            for (int nfp = 0; nfp < 2; nfp++) {
                uint32_t bh[4];
                ldsm_x4(bh, aKh + nfp * (16 * AQS * 2) + ko);
                const int n0f = nfp * 2, n1f = n0f + 1;
                mma_f16(s[n0f], ah, bh);
                mma_f16(s[n1f], ah, bh + 2);
                mma_f16(s[n0f], al, bh);
                mma_f16(s[n1f], al, bh + 2);
            }
        }

        const int rowg0 = qb * 64 + r0, rowg1 = qb * 64 + r1;
#pragma unroll
        for (int nf = 0; nf < 4; nf++) {
            const int cg = kb * 64 + wx * 32 + nf * 8 + 2 * t4;
            s[nf][0] = (cg     > rowg0) ? -1e30f : s[nf][0] * scale;
            s[nf][1] = (cg + 1 > rowg0) ? -1e30f : s[nf][1] * scale;
            s[nf][2] = (cg     > rowg1) ? -1e30f : s[nf][2] * scale;
            s[nf][3] = (cg + 1 > rowg1) ? -1e30f : s[nf][3] * scale;
        }

        float mr0 = s[0][0], mr1 = s[0][2];
#pragma unroll
        for (int nf = 0; nf < 4; nf++) {
            mr0 = fmaxf(mr0, fmaxf(s[nf][0], s[nf][1]));
            mr1 = fmaxf(mr1, fmaxf(s[nf][2], s[nf][3]));
        }
        mr0 = fmaxf(mr0, __shfl_xor_sync(0xffffffffu, mr0, 1));
        mr0 = fmaxf(mr0, __shfl_xor_sync(0xffffffffu, mr0, 2));
        mr1 = fmaxf(mr1, __shfl_xor_sync(0xffffffffu, mr1, 1));
        mr1 = fmaxf(mr1, __shfl_xor_sync(0xffffffffu, mr1, 2));
        if (t4 == 0) {
            redM[wx * 64 + r0] = mr0;
            redM[wx * 64 + r1] = mr1;
        }
        __syncthreads();
        if (kb < qb) { load_k(kb + 1); CP_COMMIT(); }

        mr0 = fmaxf(mr0, redM[(1 - wx) * 64 + r0]);
        mr1 = fmaxf(mr1, redM[(1 - wx) * 64 + r1]);

        const float mn0 = fmaxf(m_run0, mr0), mn1 = fmaxf(m_run1, mr1);
        const float co0 = __expf(m_run0 - mn0), co1 = __expf(m_run1 - mn1);
        m_run0 = mn0; m_run1 = mn1;

        float sum0 = 0.0f, sum1 = 0.0f;
#pragma unroll
        for (int nf = 0; nf < 4; nf++) {
            s[nf][0] = __expf(s[nf][0] - mn0);
            s[nf][1] = __expf(s[nf][1] - mn0);
            s[nf][2] = __expf(s[nf][2] - mn1);
            s[nf][3] = __expf(s[nf][3] - mn1);
            sum0 += s[nf][0] + s[nf][1];
            sum1 += s[nf][2] + s[nf][3];
            const int c = wx * 32 + nf * 8 + 2 * t4;
            uint32_t hw, lw;
            split2h(s[nf][0], s[nf][1], hw, lw);
            *(uint32_t*)&Phi[r0 * APS + c] = hw;
            *(uint32_t*)&Plo[r0 * APS + c] = lw;
            split2h(s[nf][2], s[nf][3], hw, lw);
            *(uint32_t*)&Phi[r1 * APS + c] = hw;
            *(uint32_t*)&Plo[r1 * APS + c] = lw;
        }
        sum0 += __shfl_xor_sync(0xffffffffu, sum0, 1);
        sum0 += __shfl_xor_sync(0xffffffffu, sum0, 2);
        sum1 += __shfl_xor_sync(0xffffffffu, sum1, 1);
        sum1 += __shfl_xor_sync(0xffffffffu, sum1, 2);
        if (t4 == 0) {
            redL[wx * 64 + r0] = sum0;
            redL[wx * 64 + r1] = sum1;
        }
        if (kb < qb) CP_WAIT1(); else CP_WAIT0();
        __syncthreads();
        l_run0 = l_run0 * co0 + redL[r0] + redL[64 + r0];
        l_run1 = l_run1 * co1 + redL[r1] + redL[64 + r1];

#pragma unroll
        for (int nf = 0; nf < 6; nf++) {
            accO[nf][0] *= co0; accO[nf][1] *= co0;
            accO[nf][2] *= co1; accO[nf][3] *= co1;
        }
#pragma unroll
        for (int ks = 0; ks < 4; ks++) {
            const uint32_t kop = ks * 32;
            const uint32_t kov = ks * (16 * AQS * 2);
            uint32_t ah[4], al[4];
            ldsm_x4(ah, aPh + kop);
            ldsm_x4(al, aPl + kop);
#pragma unroll
            for (int nfp = 0; nfp < 3; nfp++) {
                uint32_t bh[4];
                ldsm_x4_t(bh, aVh + kov + nfp * 32);
                const int n0f = nfp * 2, n1f = n0f + 1;
                mma_f16(accO[n0f], ah, bh);
                mma_f16(accO[n1f], ah, bh + 2);
                mma_f16(accO[n0f], al, bh);
                mma_f16(accO[n1f], al, bh + 2);
            }
        }
        __syncthreads();
        if (kb < qb) { load_v(kb + 1); CP_COMMIT(); }
    }

    const float il0 = 1.0f / l_run0, il1 = 1.0f / l_run1;
    const size_t row0 = (size_t)(bb * SEQ + qb * 64 + r0);
    const size_t row1 = (size_t)(bb * SEQ + qb * 64 + r1);
#pragma unroll
    for (int nf = 0; nf < 6; nf++) {
        const int c = qh * HD + wx * 48 + nf * 8 + 2 * t4;
        uint32_t h, m;
        split2h(accO[nf][0] * il0, accO[nf][1] * il0, h, m);
        *(uint32_t*)&outH[row0 * EMBED + c] = h;
        *(uint32_t*)&outM[row0 * EMBED + c] = m;
        split2h(accO[nf][2] * il1, accO[nf][3] * il1, h, m);
        *(uint32_t*)&outH[row1 * EMBED + c] = h;
        *(uint32_t*)&outM[row1 * EMBED + c] = m;
    }
}

// ---------------------------------------------------------------------------
// Launch
// ---------------------------------------------------------------------------
extern "C" void kernel_launch(void* const* d_in, const int* in_sizes, int n_in,
                              void* d_out, int out_size)
{
    const float* x         = (const float*)d_in[0];
    const int*   positions = (const int*)d_in[1];
    const float* W_qkv     = (const float*)d_in[3];
    const float* W_o       = (const float*)d_in[4];
    float* out = (float*)d_out;

    float* qkv;  cudaGetSymbolAddress((void**)&qkv,  g_qkv);
    __half *xh, *xm, *wqh, *woh, *ah, *am, *qsh, *qsm, *ksh, *vsh;
    cudaGetSymbolAddress((void**)&xh,  g_xh);   cudaGetSymbolAddress((void**)&xm,  g_xm);
    cudaGetSymbolAddress((void**)&wqh, g_wqh);  cudaGetSymbolAddress((void**)&woh, g_woh);
    cudaGetSymbolAddress((void**)&ah,  g_ah);   cudaGetSymbolAddress((void**)&am,  g_am);
    cudaGetSymbolAddress((void**)&qsh, g_qsh);  cudaGetSymbolAddress((void**)&qsm, g_qsm);
    cudaGetSymbolAddress((void**)&ksh, g_ksh);  cudaGetSymbolAddress((void**)&vsh, g_vsh);

    cudaFuncSetAttribute(attn_mma, cudaFuncAttributeMaxDynamicSharedMemorySize,
                         ATTN_SM_BYTES);
    cudaFuncSetAttribute(gemm_pre, cudaFuncAttributeMaxDynamicSharedMemorySize,
                         GEMM_SMEM_BYTES);

    // 0) convert inputs/weights
    {
        int n4;
        n4 = ROWS * EMBED / 4;
        split_kernel<<<(n4 + 255) / 256, 256>>>(x, xh, xm, n4);
        n4 = QKV_N * EMBED / 4;
        round_kernel<<<(n4 + 255) / 256, 256>>>(W_qkv, wqh, n4);
        n4 = EMBED * EMBED / 4;
        round_kernel<<<(n4 + 255) / 256, 256>>>(W_o, woh, n4);
    }

    // 1) QKV projection (fp16 2-term)
    gemm_pre<<<dim3(QKV_N / 128, ROWS / 128), 256, GEMM_SMEM_BYTES>>>(
        xh, xm, wqh, qkv, ROWS, QKV_N, EMBED);

    // 2) RoPE + convert Q (2-term), K (round); V (round)
    {
        const int totqk = ROWS * (NQ + NKV) * (HD / 2);
        rope_split_qk<<<(totqk + 255) / 256, 256>>>(qkv, positions, qsh, qsm, ksh);
        const int totv = ROWS * NKV * (HD / 4);
        round_v<<<(totv + 255) / 256, 256>>>(qkv, vsh);
    }

    // 3) Causal GQA attention -> fp16 2-term O
    attn_mma<<<dim3(SEQ / 64, NQ, BATCH), 256, ATTN_SM_BYTES>>>(
        qsh, qsm, ksh, vsh, ah, am);

    // 4) Output projection (fp16 2-term)
    gemm_pre<<<dim3(EMBED / 128, ROWS / 128), 256, GEMM_SMEM_BYTES>>>(
        ah, am, woh, out, ROWS, EMBED, EMBED);
}

// round 17
// speedup vs baseline: 2.0619x; 1.0084x over previous
#include <cuda_runtime.h>
#include <cuda_fp16.h>
#include <math.h>
#include <stdint.h>

#define EMBED 3072
#define NQ 32
#define NKV 8
#define HD 96
#define BATCH 2
#define SEQ 2048
#define ROWS (BATCH*SEQ)                 // 4096
#define QKV_N (NQ*HD + 2*NKV*HD)         // 4608
#define KOFF (NQ*HD)                     // 3072
#define VOFF (NQ*HD + NKV*HD)            // 3840

// Scratch (allocation-free rule: __device__ globals)
__device__ float g_qkv[ROWS * QKV_N];
__device__ __half g_xh[ROWS * EMBED],  g_xm[ROWS * EMBED];   // x hi/lo
__device__ __half g_wqh[QKV_N * EMBED];                      // W_qkv (rounded)
__device__ __half g_woh[EMBED * EMBED];                      // W_o (rounded)
__device__ __half g_ah[ROWS * EMBED],  g_am[ROWS * EMBED];   // attn out hi/lo
__device__ __half g_qsh[ROWS * EMBED], g_qsm[ROWS * EMBED];  // Q post-rope hi/lo
__device__ __half g_ksh[BATCH*NKV*SEQ*HD];                   // K post-rope (rounded)
__device__ __half g_vsh[BATCH*NKV*SEQ*HD];                   // V (rounded)

// ---------------------------------------------------------------------------
// Helpers
// ---------------------------------------------------------------------------
__device__ __forceinline__ uint32_t smem_u32(const void* p) {
    return (uint32_t)__cvta_generic_to_shared(p);
}

__device__ __forceinline__ void mma_f16(float* d, const uint32_t* a, const uint32_t* b) {
    asm volatile(
        "mma.sync.aligned.m16n8k16.row.col.f32.f16.f16.f32 "
        "{%0,%1,%2,%3}, {%4,%5,%6,%7}, {%8,%9}, {%0,%1,%2,%3};"
        : "+f"(d[0]), "+f"(d[1]), "+f"(d[2]), "+f"(d[3])
        : "r"(a[0]), "r"(a[1]), "r"(a[2]), "r"(a[3]), "r"(b[0]), "r"(b[1]));
}

__device__ __forceinline__ void ldsm_x4(uint32_t* r, uint32_t addr) {
    asm volatile("ldmatrix.sync.aligned.m8n8.x4.shared.b16 {%0,%1,%2,%3}, [%4];"
                 : "=r"(r[0]), "=r"(r[1]), "=r"(r[2]), "=r"(r[3]) : "r"(addr));
}

__device__ __forceinline__ void ldsm_x4_t(uint32_t* r, uint32_t addr) {
    asm volatile("ldmatrix.sync.aligned.m8n8.x4.trans.shared.b16 {%0,%1,%2,%3}, [%4];"
                 : "=r"(r[0]), "=r"(r[1]), "=r"(r[2]), "=r"(r[3]) : "r"(addr));
}

// two floats -> fp16 hi word + fp16 lo (residual) word
__device__ __forceinline__ void split2h(float x, float y, uint32_t& hi, uint32_t& lo) {
    __half hx = __float2half(x);
    __half hy = __float2half(y);
    __half lx = __float2half(x - __half2float(hx));
    __half ly = __float2half(y - __half2float(hy));
    hi = ((uint32_t)__half_as_ushort(hy) << 16) | __half_as_ushort(hx);
    lo = ((uint32_t)__half_as_ushort(ly) << 16) | __half_as_ushort(lx);
}

__device__ __forceinline__ uint32_t round2h(float x, float y) {
    return ((uint32_t)__half_as_ushort(__float2half(y)) << 16)
         | __half_as_ushort(__float2half(x));
}

__device__ __forceinline__ void cp16(void* smem_ptr, const void* gmem_ptr) {
    uint32_t s = smem_u32(smem_ptr);
    asm volatile("cp.async.cg.shared.global [%0], [%1], 16;\n" :: "r"(s), "l"(gmem_ptr));
}
#define CP_COMMIT() asm volatile("cp.async.commit_group;\n" ::: "memory")
#define CP_WAIT0()  asm volatile("cp.async.wait_group 0;\n" ::: "memory")
#define CP_WAIT1()  asm volatile("cp.async.wait_group 1;\n" ::: "memory")
#define CP_WAIT2()  asm volatile("cp.async.wait_group 2;\n" ::: "memory")

// ---------------------------------------------------------------------------
// fp32 -> fp16 hi/lo split (elementwise)
// ---------------------------------------------------------------------------
__global__ void split_kernel(const float* __restrict__ src,
                             __half* __restrict__ hi,
                             __half* __restrict__ lo, int n4)
{
    int i = blockIdx.x * blockDim.x + threadIdx.x;
    if (i >= n4) return;
    float4 v = ((const float4*)src)[i];
    uint2 h, m;
    split2h(v.x, v.y, h.x, m.x);
    split2h(v.z, v.w, h.y, m.y);
    ((uint2*)hi)[i] = h;
    ((uint2*)lo)[i] = m;
}

// fp32 -> fp16 rounding only (weights / single-precision side)
__global__ void round_kernel(const float* __restrict__ src,
                             __half* __restrict__ dst, int n4)
{
    int i = blockIdx.x * blockDim.x + threadIdx.x;
    if (i >= n4) return;
    float4 v = ((const float4*)src)[i];
    uint2 r = {round2h(v.x, v.y), round2h(v.z, v.w)};
    ((uint2*)dst)[i] = r;
}

// ---------------------------------------------------------------------------
// Fused RoPE + convert: Q (heads 0..31) -> fp16 hi/lo, K (32..39) -> fp16.
// ---------------------------------------------------------------------------
__global__ void rope_split_qk(const float* __restrict__ qkv,
                              const int* __restrict__ positions,
                              __half* __restrict__ qh_, __half* __restrict__ qm_,
                              __half* __restrict__ kh_)
{
    const int total = ROWS * (NQ + NKV) * (HD / 2);
    int idx = blockIdx.x * blockDim.x + threadIdx.x;
    if (idx >= total) return;

    const int i   = idx % (HD / 2);
    const int h   = (idx / (HD / 2)) % (NQ + NKV);
    const int row = idx / ((HD / 2) * (NQ + NKV));

    const int pos = positions[row & (SEQ - 1)];
    const float e = (float)(2 * i) / (float)HD;
    const float inv_freq = expf(-e * 9.210340371976184f);
    const float ang = (float)pos * inv_freq;
    float s, c;
    sincosf(ang, &s, &c);

    const float* base = qkv + (size_t)row * QKV_N + h * HD + i;
    const float t1 = base[0];
    const float t2 = base[HD / 2];
    const float o1 = t1 * c - t2 * s;
    const float o2 = t2 * c + t1 * s;

    if (h < NQ) {
        const size_t b = (size_t)row * EMBED + h * HD + i;
        __half h1 = __float2half(o1), h2 = __float2half(o2);
        qh_[b] = h1;
        qh_[b + HD/2] = h2;
        qm_[b] = __float2half(o1 - __half2float(h1));
        qm_[b + HD/2] = __float2half(o2 - __half2float(h2));
    } else {
        const int kvh = h - NQ;
        const int bb = row >> 11, ss = row & (SEQ - 1);
        const size_t b = ((size_t)(bb * NKV + kvh) * SEQ + ss) * HD + i;
        kh_[b] = __float2half(o1);
        kh_[b + HD/2] = __float2half(o2);
    }
}

// ---------------------------------------------------------------------------
// V: round to fp16, row-major [(bb*8+kvh)*2048+s][96].
// ---------------------------------------------------------------------------
__global__ void round_v(const float* __restrict__ qkv,
                        __half* __restrict__ vh_)
{
    const int total = ROWS * NKV * (HD / 4);
    int idx = blockIdx.x * blockDim.x + threadIdx.x;
    if (idx >= total) return;
    const int d4  = idx % (HD / 4);
    const int kvh = (idx / (HD / 4)) % NKV;
    const int row = idx / ((HD / 4) * NKV);
    const int bb = row >> 11, ss = row & (SEQ - 1);

    float4 v = *(const float4*)(qkv + (size_t)row * QKV_N + VOFF + kvh * HD + d4 * 4);
    const size_t b = ((size_t)(bb * NKV + kvh) * SEQ + ss) * HD + d4 * 4;
    uint2 r = {round2h(v.x, v.y), round2h(v.z, v.w)};
    *(uint2*)&vh_[b] = r;
}

// ---------------------------------------------------------------------------
// fp16 2-term GEMM: C = (Ahi+Alo) * Bh^T.  BK=16, 4 cp.async stages,
// prefetch distance 3. CTA 128x128, 8 warps (4x2).
// Inner loop: all 4 B fragments loaded up-front; hi-pass over all 16
// accumulator tiles then lo-pass -> same-acc HMMA distance 16 (was 4).
// ---------------------------------------------------------------------------
#define BM 128
#define BN 128
#define BK 16
#define SB 24                     // stride 24 fp16 = 12 banks -> conflict-free
#define ARR (128 * SB)
#define STG (3 * ARR)             // Ahi, Alo, Bh
#define NSTAGE 4
#define GEMM_SMEM_BYTES (NSTAGE * STG * 2)   // 73,728 B

__global__ __launch_bounds__(256, 2) void gemm_pre(const __half* __restrict__ Ah,
                                                   const __half* __restrict__ Al,
                                                   const __half* __restrict__ Bh,
                                                   float* __restrict__ C,
                                                   int M, int N, int K)
{
    extern __shared__ __half smem[];

    const int tid  = threadIdx.x;
    const int warp = tid >> 5;
    const int lane = tid & 31;
    const int m0 = blockIdx.y * BM;
    const int n0 = blockIdx.x * BN;

    const int wm = (warp >> 1) * 32;
    const int wn = (warp & 1) * 64;
    const int g  = lane >> 2;
    const int t4 = lane & 3;

    const int l7   = lane & 7;
    const int l8r  = lane & 8;
    const int l16h = (lane & 16) >> 1;

    const int lrow = tid >> 1;
    const int lco  = (tid & 1) * 8;

    float acc[2][8][4];
#pragma unroll
    for (int mf = 0; mf < 2; mf++)
#pragma unroll
        for (int nf = 0; nf < 8; nf++)
#pragma unroll
            for (int r = 0; r < 4; r++) acc[mf][nf][r] = 0.0f;

    const size_t arow = (size_t)(m0 + lrow) * K;
    const size_t brow = (size_t)(n0 + lrow) * K;

    auto load_tile = [&](int k0, int stage) {
        __half* s = smem + stage * STG;
        const int so = lrow * SB + lco;
        cp16(&s[so],         Ah + arow + k0 + lco);
        cp16(&s[ARR + so],   Al + arow + k0 + lco);
        cp16(&s[2*ARR + so], Bh + brow + k0 + lco);
    };

    const int T = K / BK;   // 192
    load_tile(0, 0);        CP_COMMIT();
    load_tile(BK, 1);       CP_COMMIT();
    load_tile(2 * BK, 2);   CP_COMMIT();

    for (int t = 0; t < T; t++) {
        CP_WAIT2();
        __syncthreads();
        if (t + 3 < T) load_tile((t + 3) * BK, (t + 3) & 3);
        CP_COMMIT();     // possibly-empty group keeps the accounting exact

        const __half* base = smem + (t & 3) * STG;
        const uint32_t aAh = smem_u32(base) + ((wm + l7 + l8r) * SB + l16h) * 2;
        const uint32_t aAl = aAh + ARR * 2;
        const uint32_t aBh = smem_u32(base) + (2 * ARR + (wn + l7 + l16h) * SB + l8r) * 2;

        uint32_t ahi[2][4], alo[2][4];
        ldsm_x4(ahi[0], aAh);
        ldsm_x4(ahi[1], aAh + (16 * SB * 2));
        ldsm_x4(alo[0], aAl);
        ldsm_x4(alo[1], aAl + (16 * SB * 2));

        uint32_t bh[4][4];
#pragma unroll
        for (int nfp = 0; nfp < 4; nfp++)
            ldsm_x4(bh[nfp], aBh + nfp * (16 * SB * 2));

        // hi pass: 16 distinct accumulator tiles
#pragma unroll
        for (int nfp = 0; nfp < 4; nfp++) {
            const int n0f = nfp * 2, n1f = n0f + 1;
            mma_f16(acc[0][n0f], ahi[0], bh[nfp]);
            mma_f16(acc[1][n0f], ahi[1], bh[nfp]);
            mma_f16(acc[0][n1f], ahi[0], bh[nfp] + 2);
            mma_f16(acc[1][n1f], ahi[1], bh[nfp] + 2);
        }
        // lo pass: same tiles, reuse distance = 16 MMAs
#pragma unroll
        for (int nfp = 0; nfp < 4; nfp++) {
            const int n0f = nfp * 2, n1f = n0f + 1;
            mma_f16(acc[0][n0f], alo[0], bh[nfp]);
            mma_f16(acc[1][n0f], alo[1], bh[nfp]);
            mma_f16(acc[0][n1f], alo[0], bh[nfp] + 2);
            mma_f16(acc[1][n1f], alo[1], bh[nfp] + 2);
        }
    }

#pragma unroll
    for (int mf = 0; mf < 2; mf++) {
#pragma unroll
        for (int nf = 0; nf < 8; nf++) {
            const int r = m0 + wm + mf * 16 + g;
            const int c = n0 + wn + nf * 8 + 2 * t4;
            float2 v0 = {acc[mf][nf][0], acc[mf][nf][1]};
            float2 v1 = {acc[mf][nf][2], acc[mf][nf][3]};
            *(float2*)(C + (size_t)r * N + c)       = v0;
            *(float2*)(C + (size_t)(r + 8) * N + c) = v1;
        }
    }
}

// ---------------------------------------------------------------------------
// Causal GQA flash attention: Q 2-term fp16, K/V single fp16 (unchanged).
// ---------------------------------------------------------------------------
#define AQS 104
#define APS 72
#define ATTN_SM_BYTES ((4*64*AQS + 2*64*APS) * 2 + 2 * 128 * 4)   // 72,704 B

__global__ __launch_bounds__(256, 2) void attn_mma(
    const __half* __restrict__ qh_, const __half* __restrict__ qm_,
    const __half* __restrict__ kh_, const __half* __restrict__ vh_,
    __half* __restrict__ outH, __half* __restrict__ outM)
{
    extern __shared__ char sm_raw[];
    __half* Qhi = (__half*)sm_raw;
    __half* Qlo = Qhi + 64 * AQS;
    __half* Khi = Qlo + 64 * AQS;
    __half* Vhi = Khi + 64 * AQS;
    __half* Phi = Vhi + 64 * AQS;
    __half* Plo = Phi + 64 * APS;
    float* redM = (float*)(Plo + 64 * APS);
    float* redL = redM + 128;

    const int qb = blockIdx.x;
    const int qh = blockIdx.y;
    const int bb = blockIdx.z;
    const int kvh = qh >> 2;
    const int tid = threadIdx.x, warp = tid >> 5, lane = tid & 31;
    const int wy = warp >> 1, wx = warp & 1;
    const int g = lane >> 2, t4 = lane & 3;
    const int r0 = wy * 16 + g, r1 = r0 + 8;
    const float scale = 0.10206207261596577f;

    const int l7   = lane & 7;
    const int l8r  = lane & 8;
    const int l16h = (lane & 16) >> 1;

    const uint32_t aQh = smem_u32(Qhi) + ((wy * 16 + l7 + l8r) * AQS + l16h) * 2;
    const uint32_t aQl = aQh + (64 * AQS) * 2;
    const uint32_t aKh = smem_u32(Khi) + ((wx * 32 + l7 + l16h) * AQS + l8r) * 2;
    const uint32_t aVh = smem_u32(Vhi) + ((l7 + l8r) * AQS + wx * 48 + l16h) * 2;
    const uint32_t aPh = smem_u32(Phi) + ((wy * 16 + l7 + l8r) * APS + l16h) * 2;
    const uint32_t aPl = aPh + (64 * APS) * 2;

    const __half* qsrcH = qh_ + (size_t)(bb * SEQ + qb * 64) * EMBED + qh * HD;
    const __half* qsrcM = qm_ + (size_t)(bb * SEQ + qb * 64) * EMBED + qh * HD;
    const size_t kvbase = (size_t)(bb * NKV + kvh) * SEQ * HD;

    auto load_q = [&]() {
#pragma unroll
        for (int j = 0; j < 3; j++) {
            const int idx = tid + j * 256;
            const int r = idx / 12, c = idx % 12;
            cp16(&Qhi[r * AQS + c * 8], qsrcH + (size_t)r * EMBED + c * 8);
            cp16(&Qlo[r * AQS + c * 8], qsrcM + (size_t)r * EMBED + c * 8);
        }
    };
    auto load_k = [&](int kb) {
        const __half* sh = kh_ + kvbase + (size_t)kb * 64 * HD;
#pragma unroll
        for (int j = 0; j < 3; j++) {
            const int idx = tid + j * 256;
            const int r = idx / 12, c = idx % 12;
            cp16(&Khi[r * AQS + c * 8], sh + r * HD + c * 8);
        }
    };
    auto load_v = [&](int kb) {
        const __half* sh = vh_ + kvbase + (size_t)kb * 64 * HD;
#pragma unroll
        for (int j = 0; j < 3; j++) {
            const int idx = tid + j * 256;
            const int r = idx / 12, c = idx % 12;
            cp16(&Vhi[r * AQS + c * 8], sh + r * HD + c * 8);
        }
    };

    load_q();
    load_k(0);
    CP_COMMIT();
    load_v(0);
    CP_COMMIT();

    float accO[6][4];
#pragma unroll
    for (int nf = 0; nf < 6; nf++)
#pragma unroll
        for (int e = 0; e < 4; e++) accO[nf][e] = 0.0f;
    float m_run0 = -1e30f, m_run1 = -1e30f, l_run0 = 0.0f, l_run1 = 0.0f;

    for (int kb = 0; kb <= qb; kb++) {
        CP_WAIT1();
        __syncthreads();

        float s[4][4];
#pragma unroll
        for (int nf = 0; nf < 4; nf++)
#pragma unroll
            for (int e = 0; e < 4; e++) s[nf][e] = 0.0f;

#pragma unroll
        for (int ks = 0; ks < 6; ks++) {
            const uint32_t ko = ks * 32;
            uint32_t ah[4], al[4];
            ldsm_x4(ah, aQh + ko);
            ldsm_x4(al, aQl + ko);
#pragma unroll
            for (int nfp = 0; nfp < 2; nfp++) {
                uint32_t bh[4];
                ldsm_x4(bh, aKh + nfp * (16 * AQS * 2) + ko);
                const int n0f = nfp * 2, n1f = n0f + 1;
                mma_f16(s[n0f], ah, bh);
                mma_f16(s[n1f], ah, bh + 2);
                mma_f16(s[n0f], al, bh);
                mma_f16(s[n1f], al, bh + 2);
            }
        }

        const int rowg0 = qb * 64 + r0, rowg1 = qb * 64 + r1;
#pragma unroll
        for (int nf = 0; nf < 4; nf++) {
            const int cg = kb * 64 + wx * 32 + nf * 8 + 2 * t4;
            s[nf][0] = (cg     > rowg0) ? -1e30f : s[nf][0] * scale;
            s[nf][1] = (cg + 1 > rowg0) ? -1e30f : s[nf][1] * scale;
            s[nf][2] = (cg     > rowg1) ? -1e30f : s[nf][2] * scale;
            s[nf][3] = (cg + 1 > rowg1) ? -1e30f : s[nf][3] * scale;
        }

        float mr0 = s[0][0], mr1 = s[0][2];
#pragma unroll
        for (int nf = 0; nf < 4; nf++) {
            mr0 = fmaxf(mr0, fmaxf(s[nf][0], s[nf][1]));
            mr1 = fmaxf(mr1, fmaxf(s[nf][2], s[nf][3]));
        }
        mr0 = fmaxf(mr0, __shfl_xor_sync(0xffffffffu, mr0, 1));
        mr0 = fmaxf(mr0, __shfl_xor_sync(0xffffffffu, mr0, 2));
        mr1 = fmaxf(mr1, __shfl_xor_sync(0xffffffffu, mr1, 1));
        mr1 = fmaxf(mr1, __shfl_xor_sync(0xffffffffu, mr1, 2));
        if (t4 == 0) {
            redM[wx * 64 + r0] = mr0;
            redM[wx * 64 + r1] = mr1;
        }
        __syncthreads();
        if (kb < qb) { load_k(kb + 1); CP_COMMIT(); }

        mr0 = fmaxf(mr0, redM[(1 - wx) * 64 + r0]);
        mr1 = fmaxf(mr1, redM[(1 - wx) * 64 + r1]);

        const float mn0 = fmaxf(m_run0, mr0), mn1 = fmaxf(m_run1, mr1);
        const float co0 = __expf(m_run0 - mn0), co1 = __expf(m_run1 - mn1);
        m_run0 = mn0; m_run1 = mn1;

        float sum0 = 0.0f, sum1 = 0.0f;
#pragma unroll
        for (int nf = 0; nf < 4; nf++) {
            s[nf][0] = __expf(s[nf][0] - mn0);
            s[nf][1] = __expf(s[nf][1] - mn0);
            s[nf][2] = __expf(s[nf][2] - mn1);
            s[nf][3] = __expf(s[nf][3] - mn1);
            sum0 += s[nf][0] + s[nf][1];
            sum1 += s[nf][2] + s[nf][3];
            const int c = wx * 32 + nf * 8 + 2 * t4;
            uint32_t hw, lw;
            split2h(s[nf][0], s[nf][1], hw, lw);
            *(uint32_t*)&Phi[r0 * APS + c] = hw;
            *(uint32_t*)&Plo[r0 * APS + c] = lw;
            split2h(s[nf][2], s[nf][3], hw, lw);
            *(uint32_t*)&Phi[r1 * APS + c] = hw;
            *(uint32_t*)&Plo[r1 * APS + c] = lw;
        }
        sum0 += __shfl_xor_sync(0xffffffffu, sum0, 1);
        sum0 += __shfl_xor_sync(0xffffffffu, sum0, 2);
        sum1 += __shfl_xor_sync(0xffffffffu, sum1, 1);
        sum1 += __shfl_xor_sync(0xffffffffu, sum1, 2);
        if (t4 == 0) {
            redL[wx * 64 + r0] = sum0;
            redL[wx * 64 + r1] = sum1;
        }
        if (kb < qb) CP_WAIT1(); else CP_WAIT0();
        __syncthreads();
        l_run0 = l_run0 * co0 + redL[r0] + redL[64 + r0];
        l_run1 = l_run1 * co1 + redL[r1] + redL[64 + r1];

#pragma unroll
        for (int nf = 0; nf < 6; nf++) {
            accO[nf][0] *= co0; accO[nf][1] *= co0;
            accO[nf][2] *= co1; accO[nf][3] *= co1;
        }
#pragma unroll
        for (int ks = 0; ks < 4; ks++) {
            const uint32_t kop = ks * 32;
            const uint32_t kov = ks * (16 * AQS * 2);
            uint32_t ah[4], al[4];
            ldsm_x4(ah, aPh + kop);
            ldsm_x4(al, aPl + kop);
#pragma unroll
            for (int nfp = 0; nfp < 3; nfp++) {
                uint32_t bh[4];
                ldsm_x4_t(bh, aVh + kov + nfp * 32);
                const int n0f = nfp * 2, n1f = n0f + 1;
                mma_f16(accO[n0f], ah, bh);
                mma_f16(accO[n1f], ah, bh + 2);
                mma_f16(accO[n0f], al, bh);
                mma_f16(accO[n1f], al, bh + 2);
            }
        }
        __syncthreads();
        if (kb < qb) { load_v(kb + 1); CP_COMMIT(); }
    }

    const float il0 = 1.0f / l_run0, il1 = 1.0f / l_run1;
    const size_t row0 = (size_t)(bb * SEQ + qb * 64 + r0);
    const size_t row1 = (size_t)(bb * SEQ + qb * 64 + r1);
#pragma unroll
    for (int nf = 0; nf < 6; nf++) {
        const int c = qh * HD + wx * 48 + nf * 8 + 2 * t4;
        uint32_t h, m;
        split2h(accO[nf][0] * il0, accO[nf][1] * il0, h, m);
        *(uint32_t*)&outH[row0 * EMBED + c] = h;
        *(uint32_t*)&outM[row0 * EMBED + c] = m;
        split2h(accO[nf][2] * il1, accO[nf][3] * il1, h, m);
        *(uint32_t*)&outH[row1 * EMBED + c] = h;
        *(uint32_t*)&outM[row1 * EMBED + c] = m;
    }
}

// ---------------------------------------------------------------------------
// Launch
// ---------------------------------------------------------------------------
extern "C" void kernel_launch(void* const* d_in, const int* in_sizes, int n_in,
                              void* d_out, int out_size)
{
    const float* x         = (const float*)d_in[0];
    const int*   positions = (const int*)d_in[1];
    const float* W_qkv     = (const float*)d_in[3];
    const float* W_o       = (const float*)d_in[4];
    float* out = (float*)d_out;

    float* qkv;  cudaGetSymbolAddress((void**)&qkv,  g_qkv);
    __half *xh, *xm, *wqh, *woh, *ah, *am, *qsh, *qsm, *ksh, *vsh;
    cudaGetSymbolAddress((void**)&xh,  g_xh);   cudaGetSymbolAddress((void**)&xm,  g_xm);
    cudaGetSymbolAddress((void**)&wqh, g_wqh);  cudaGetSymbolAddress((void**)&woh, g_woh);
    cudaGetSymbolAddress((void**)&ah,  g_ah);   cudaGetSymbolAddress((void**)&am,  g_am);
    cudaGetSymbolAddress((void**)&qsh, g_qsh);  cudaGetSymbolAddress((void**)&qsm, g_qsm);
    cudaGetSymbolAddress((void**)&ksh, g_ksh);  cudaGetSymbolAddress((void**)&vsh, g_vsh);

    cudaFuncSetAttribute(attn_mma, cudaFuncAttributeMaxDynamicSharedMemorySize,
                         ATTN_SM_BYTES);
    cudaFuncSetAttribute(gemm_pre, cudaFuncAttributeMaxDynamicSharedMemorySize,
                         GEMM_SMEM_BYTES);

    // 0) convert inputs/weights
    {
        int n4;
        n4 = ROWS * EMBED / 4;
        split_kernel<<<(n4 + 255) / 256, 256>>>(x, xh, xm, n4);
        n4 = QKV_N * EMBED / 4;
        round_kernel<<<(n4 + 255) / 256, 256>>>(W_qkv, wqh, n4);
        n4 = EMBED * EMBED / 4;
        round_kernel<<<(n4 + 255) / 256, 256>>>(W_o, woh, n4);
    }

    // 1) QKV projection (fp16 2-term)
    gemm_pre<<<dim3(QKV_N / 128, ROWS / 128), 256, GEMM_SMEM_BYTES>>>(
        xh, xm, wqh, qkv, ROWS, QKV_N, EMBED);

    // 2) RoPE + convert Q (2-term), K (round); V (round)
    {
        const int totqk = ROWS * (NQ + NKV) * (HD / 2);
        rope_split_qk<<<(totqk + 255) / 256, 256>>>(qkv, positions, qsh, qsm, ksh);
        const int totv = ROWS * NKV * (HD / 4);
        round_v<<<(totv + 255) / 256, 256>>>(qkv, vsh);
    }

    // 3) Causal GQA attention -> fp16 2-term O
    attn_mma<<<dim3(SEQ / 64, NQ, BATCH), 256, ATTN_SM_BYTES>>>(
        qsh, qsm, ksh, vsh, ah, am);

    // 4) Output projection (fp16 2-term)
    gemm_pre<<<dim3(EMBED / 128, ROWS / 128), 256, GEMM_SMEM_BYTES>>>(
        ah, am, woh, out, ROWS, EMBED, EMBED);
}